// round 1
// baseline (speedup 1.0000x reference)
#include <cuda_runtime.h>
#include <math.h>

#define Bm   2
#define Sm   2048
#define Dm   1024
#define Hm   16
#define DHm  64
#define MROWS (Bm*Sm)      // 4096
#define QKVN  (3*Dm)       // 3072

// ---------------- scratch (device globals; no allocation) ----------------
__device__ float g_qkv[MROWS * QKVN];     // [B*S, 3072]  (q|k|v, each [H,Dh])
__device__ float g_q  [Bm*Hm*Sm*DHm];     // [B,H,S,Dh] (rope'd)
__device__ float g_k  [Bm*Hm*Sm*DHm];     // [B,H,S,Dh] (rope'd)
__device__ float g_ctx[MROWS * Dm];       // [B*S, D]
__device__ float g_cos[Sm * DHm];
__device__ float g_sin[Sm * DHm];

// ---------------- RoPE cos/sin table ----------------
__global__ void rope_table_kernel() {
    int idx = blockIdx.x * blockDim.x + threadIdx.x;
    if (idx >= Sm * DHm) return;
    int s = idx >> 6, d = idx & 63, i = d & 31;
    double inv = pow(10000.0, -(double)(2 * i) / 64.0);
    double ang = fmod((double)s * inv, 6.283185307179586476925287);
    double sn, cs;
    sincos(ang, &sn, &cs);
    g_cos[idx] = (float)cs;
    g_sin[idx] = (float)sn;
}

// ---------------- RoPE apply + transpose to [B,H,S,Dh] ----------------
__global__ void rope_apply_kernel() {
    int idx = blockIdx.x * blockDim.x + threadIdx.x;   // B*S*H*Dh = 2^22
    int d = idx & 63;
    int h = (idx >> 6) & 15;
    int s = (idx >> 10) & 2047;
    int b = idx >> 21;
    int base = (b * Sm + s) * QKVN + h * DHm;
    float c  = g_cos[(s << 6) + d];
    float sn = g_sin[(s << 6) + d];
    int dp = d ^ 32;
    float sgn = (d < 32) ? -1.0f : 1.0f;
    float q  = g_qkv[base + d];
    float qp = g_qkv[base + dp];
    float k  = g_qkv[base + Dm + d];
    float kp = g_qkv[base + Dm + dp];
    int o = ((b * Hm + h) * Sm + s) * DHm + d;
    g_q[o] = fmaf(q, c, sgn * qp * sn);
    g_k[o] = fmaf(k, c, sgn * kp * sn);
}

// ---------------- SGEMM: C[m,n] = sum_k A[m,k]*Bw[n,k] + bias[n] ----------------
// A row-major [M,K], Bw row-major [N,K]. Tiles 128x128xBK8, 256 thr, 8x8 micro.
__global__ __launch_bounds__(256)
void sgemm_bias_kernel(const float* __restrict__ A, const float* __restrict__ Bw,
                       const float* __restrict__ bias, float* __restrict__ C,
                       int M, int N, int K)
{
    __shared__ float As[8][132];
    __shared__ float Bs[8][132];
    int tid = threadIdx.x;
    int tx = tid & 15, ty = tid >> 4;
    int m0 = blockIdx.y * 128, n0 = blockIdx.x * 128;

    float acc[8][8];
#pragma unroll
    for (int i = 0; i < 8; i++)
#pragma unroll
        for (int j = 0; j < 8; j++) acc[i][j] = 0.0f;

    int lrow = tid >> 1;
    int lcol = (tid & 1) * 4;
    const float* Aptr = A + (size_t)(m0 + lrow) * K + lcol;
    const float* Bptr = Bw + (size_t)(n0 + lrow) * K + lcol;

    for (int k0 = 0; k0 < K; k0 += 8) {
        float4 av = *(const float4*)(Aptr + k0);
        float4 bv = *(const float4*)(Bptr + k0);
        As[lcol + 0][lrow] = av.x; As[lcol + 1][lrow] = av.y;
        As[lcol + 2][lrow] = av.z; As[lcol + 3][lrow] = av.w;
        Bs[lcol + 0][lrow] = bv.x; Bs[lcol + 1][lrow] = bv.y;
        Bs[lcol + 2][lrow] = bv.z; Bs[lcol + 3][lrow] = bv.w;
        __syncthreads();
#pragma unroll
        for (int kk = 0; kk < 8; kk++) {
            float a[8], b[8];
#pragma unroll
            for (int i = 0; i < 8; i++) a[i] = As[kk][ty + i * 16];
#pragma unroll
            for (int j = 0; j < 8; j++) b[j] = Bs[kk][tx + j * 16];
#pragma unroll
            for (int i = 0; i < 8; i++)
#pragma unroll
                for (int j = 0; j < 8; j++)
                    acc[i][j] = fmaf(a[i], b[j], acc[i][j]);
        }
        __syncthreads();
    }
#pragma unroll
    for (int j = 0; j < 8; j++) {
        float bb = bias[n0 + tx + j * 16];
#pragma unroll
        for (int i = 0; i < 8; i++)
            C[(size_t)(m0 + ty + i * 16) * N + n0 + tx + j * 16] = acc[i][j] + bb;
    }
}

// ---------------- Flash attention (causal), 64x64 tiles, fp32 ----------------
#define TP 68   // padded smem row stride (floats); 68*4 bytes % 16 == 0

__global__ __launch_bounds__(256)
void attn_kernel() {
    extern __shared__ float smf[];
    float* Qs  = smf;                 // [64][TP]  rows x d
    float* Kst = smf + 64 * TP;       // [64][TP]  d x cols (transposed)
    float* Vs  = smf + 2 * 64 * TP;   // [64][TP]  rows x d
    float* Ps  = smf + 3 * 64 * TP;   // [64][TP]  rows x cols

    int tid = threadIdx.x;
    int tx = tid & 15, ty = tid >> 4;
    int bh = blockIdx.y;
    int b = bh >> 4, h = bh & 15;
    int i0 = blockIdx.x * 64;
    const float scale = 0.125f;   // 1/sqrt(64)

    // load Q tile (rope'd), rows i0..i0+63
    for (int it = tid; it < 1024; it += 256) {
        int r = it >> 4, c4 = (it & 15) << 2;
        float4 v = *(const float4*)&g_q[((size_t)bh * Sm + i0 + r) * DHm + c4];
        *(float4*)&Qs[r * TP + c4] = v;
    }

    float m[4], l[4], o[4][4];
#pragma unroll
    for (int i = 0; i < 4; i++) {
        m[i] = -INFINITY; l[i] = 0.0f;
#pragma unroll
        for (int j = 0; j < 4; j++) o[i][j] = 0.0f;
    }

    for (int j0 = 0; j0 <= i0; j0 += 64) {
        __syncthreads();   // protect Kst/Vs reuse (and Q store on first iter)
        // load K tile transposed + V tile
        for (int it = tid; it < 1024; it += 256) {
            int r = it >> 4, c4 = (it & 15) << 2;
            float4 kv = *(const float4*)&g_k[((size_t)bh * Sm + j0 + r) * DHm + c4];
            Kst[(c4 + 0) * TP + r] = kv.x;
            Kst[(c4 + 1) * TP + r] = kv.y;
            Kst[(c4 + 2) * TP + r] = kv.z;
            Kst[(c4 + 3) * TP + r] = kv.w;
            float4 vv = *(const float4*)&g_qkv[(size_t)(b * Sm + j0 + r) * QKVN
                                               + 2 * Dm + h * DHm + c4];
            *(float4*)&Vs[r * TP + c4] = vv;
        }
        __syncthreads();

        // S = Q K^T  (each thread 4 rows x 4 cols)
        float sacc[4][4];
#pragma unroll
        for (int i = 0; i < 4; i++)
#pragma unroll
            for (int j = 0; j < 4; j++) sacc[i][j] = 0.0f;

#pragma unroll 4
        for (int kk = 0; kk < 64; kk++) {
            float4 kf = *(float4*)&Kst[kk * TP + tx * 4];
            float kr[4] = {kf.x, kf.y, kf.z, kf.w};
            float qr[4];
#pragma unroll
            for (int i = 0; i < 4; i++) qr[i] = Qs[(ty * 4 + i) * TP + kk];
#pragma unroll
            for (int i = 0; i < 4; i++)
#pragma unroll
                for (int j = 0; j < 4; j++)
                    sacc[i][j] = fmaf(qr[i], kr[j], sacc[i][j]);
        }

        bool diag = (j0 == i0);
        // online softmax per row (row owned by 16 lanes: same ty, tx=0..15)
#pragma unroll
        for (int i = 0; i < 4; i++) {
            int r = ty * 4 + i;
            float p[4];
#pragma unroll
            for (int j = 0; j < 4; j++) {
                float sv = sacc[i][j] * scale;
                if (diag && (tx * 4 + j) > r) sv = -INFINITY;
                p[j] = sv;
            }
            float mt = fmaxf(fmaxf(p[0], p[1]), fmaxf(p[2], p[3]));
            mt = fmaxf(mt, __shfl_xor_sync(0xffffffffu, mt, 8));
            mt = fmaxf(mt, __shfl_xor_sync(0xffffffffu, mt, 4));
            mt = fmaxf(mt, __shfl_xor_sync(0xffffffffu, mt, 2));
            mt = fmaxf(mt, __shfl_xor_sync(0xffffffffu, mt, 1));
            float mnew  = fmaxf(m[i], mt);
            float alpha = __expf(m[i] - mnew);
            float rs = 0.0f;
#pragma unroll
            for (int j = 0; j < 4; j++) { p[j] = __expf(p[j] - mnew); rs += p[j]; }
            rs += __shfl_xor_sync(0xffffffffu, rs, 8);
            rs += __shfl_xor_sync(0xffffffffu, rs, 4);
            rs += __shfl_xor_sync(0xffffffffu, rs, 2);
            rs += __shfl_xor_sync(0xffffffffu, rs, 1);
            l[i] = l[i] * alpha + rs;
            m[i] = mnew;
#pragma unroll
            for (int j = 0; j < 4; j++) o[i][j] *= alpha;
            *(float4*)&Ps[r * TP + tx * 4] = make_float4(p[0], p[1], p[2], p[3]);
        }
        __syncthreads();

        // O += P V
#pragma unroll 4
        for (int c = 0; c < 64; c++) {
            float4 vf = *(float4*)&Vs[c * TP + tx * 4];
            float vr[4] = {vf.x, vf.y, vf.z, vf.w};
            float pr[4];
#pragma unroll
            for (int i = 0; i < 4; i++) pr[i] = Ps[(ty * 4 + i) * TP + c];
#pragma unroll
            for (int i = 0; i < 4; i++)
#pragma unroll
                for (int j = 0; j < 4; j++)
                    o[i][j] = fmaf(pr[i], vr[j], o[i][j]);
        }
    }

    // write context in [B, S, H*Dh] layout
#pragma unroll
    for (int i = 0; i < 4; i++) {
        float invl = 1.0f / l[i];
        float4 ov = make_float4(o[i][0] * invl, o[i][1] * invl,
                                o[i][2] * invl, o[i][3] * invl);
        *(float4*)&g_ctx[(size_t)(b * Sm + i0 + ty * 4 + i) * Dm + h * DHm + tx * 4] = ov;
    }
}

// ---------------- launch ----------------
extern "C" void kernel_launch(void* const* d_in, const int* in_sizes, int n_in,
                              void* d_out, int out_size)
{
    const float* x      = (const float*)d_in[0];
    const float* qkv_w  = (const float*)d_in[1];
    const float* qkv_b  = (const float*)d_in[2];
    const float* proj_w = (const float*)d_in[3];
    const float* proj_b = (const float*)d_in[4];
    float* out = (float*)d_out;

    float *p_qkv, *p_ctx;
    cudaGetSymbolAddress((void**)&p_qkv, g_qkv);
    cudaGetSymbolAddress((void**)&p_ctx, g_ctx);

    int smem_attn = 4 * 64 * TP * sizeof(float);   // 69632
    cudaFuncSetAttribute(attn_kernel, cudaFuncAttributeMaxDynamicSharedMemorySize, smem_attn);

    // 1) QKV GEMM: [4096,1024] x [3072,1024]^T -> g_qkv
    sgemm_bias_kernel<<<dim3(QKVN / 128, MROWS / 128), 256>>>(
        x, qkv_w, qkv_b, p_qkv, MROWS, QKVN, Dm);

    // 2) RoPE table + apply (-> g_q, g_k in [B,H,S,Dh])
    rope_table_kernel<<<(Sm * DHm + 255) / 256, 256>>>();
    rope_apply_kernel<<<(Bm * Sm * Hm * DHm) / 256, 256>>>();

    // 3) causal flash attention -> g_ctx [B,S,D]
    attn_kernel<<<dim3(Sm / 64, Bm * Hm), 256, smem_attn>>>();

    // 4) output projection: [4096,1024] x [1024,1024]^T + b -> out
    sgemm_bias_kernel<<<dim3(Dm / 128, MROWS / 128), 256>>>(
        p_ctx, proj_w, proj_b, out, MROWS, Dm, Dm);
}

// round 3
// speedup vs baseline: 1.5812x; 1.5812x over previous
#include <cuda_runtime.h>
#include <cuda_bf16.h>
#include <math.h>
#include <stdint.h>

#define Bm   2
#define Sm   2048
#define Dm   1024
#define Hm   16
#define DHm  64
#define MROWS (Bm*Sm)      // 4096
#define QKVN  (3*Dm)       // 3072

// ---------------- scratch (device globals; no allocation) ----------------
__device__ float g_qkv[MROWS * QKVN];     // [B*S, 3072]  (q|k|v, each [H,Dh])
__device__ float g_q  [Bm*Hm*Sm*DHm];     // [B,H,S,Dh] (rope'd)
__device__ float g_k  [Bm*Hm*Sm*DHm];     // [B,H,S,Dh] (rope'd)
__device__ float g_ctx[MROWS * Dm];       // [B*S, D]
__device__ float g_cos[Sm * DHm];
__device__ float g_sin[Sm * DHm];

// bf16 split buffers
__device__ __nv_bfloat16 g_xh [MROWS * Dm];
__device__ __nv_bfloat16 g_xl [MROWS * Dm];
__device__ __nv_bfloat16 g_wh [QKVN * Dm];
__device__ __nv_bfloat16 g_wl [QKVN * Dm];
__device__ __nv_bfloat16 g_ch [MROWS * Dm];
__device__ __nv_bfloat16 g_cl [MROWS * Dm];
__device__ __nv_bfloat16 g_ph [Dm * Dm];
__device__ __nv_bfloat16 g_pl [Dm * Dm];

// ---------------- helpers ----------------
__device__ __forceinline__ uint32_t smem_u32(const void* p) {
    uint32_t a;
    asm("{ .reg .u64 t; cvta.to.shared.u64 t, %1; cvt.u32.u64 %0, t; }" : "=r"(a) : "l"(p));
    return a;
}
__device__ __forceinline__ void ldsm4(uint32_t* r, uint32_t addr) {
    asm volatile("ldmatrix.sync.aligned.m8n8.x4.shared.b16 {%0,%1,%2,%3}, [%4];"
                 : "=r"(r[0]), "=r"(r[1]), "=r"(r[2]), "=r"(r[3]) : "r"(addr));
}
__device__ __forceinline__ void mma16816(float* c, const uint32_t* a, uint32_t b0, uint32_t b1) {
    asm volatile("mma.sync.aligned.m16n8k16.row.col.f32.bf16.bf16.f32 "
                 "{%0,%1,%2,%3}, {%4,%5,%6,%7}, {%8,%9}, {%0,%1,%2,%3};"
                 : "+f"(c[0]), "+f"(c[1]), "+f"(c[2]), "+f"(c[3])
                 : "r"(a[0]), "r"(a[1]), "r"(a[2]), "r"(a[3]), "r"(b0), "r"(b1));
}

// ---------------- split conversion ----------------
__global__ void split_kernel(const float* __restrict__ src, __nv_bfloat16* __restrict__ hi,
                             __nv_bfloat16* __restrict__ lo, int n4) {
    int i = blockIdx.x * blockDim.x + threadIdx.x;
    if (i >= n4) return;
    float4 v = ((const float4*)src)[i];
    __nv_bfloat16 h0 = __float2bfloat16(v.x), h1 = __float2bfloat16(v.y);
    __nv_bfloat16 h2 = __float2bfloat16(v.z), h3 = __float2bfloat16(v.w);
    __nv_bfloat16 l0 = __float2bfloat16(v.x - __bfloat162float(h0));
    __nv_bfloat16 l1 = __float2bfloat16(v.y - __bfloat162float(h1));
    __nv_bfloat16 l2 = __float2bfloat16(v.z - __bfloat162float(h2));
    __nv_bfloat16 l3 = __float2bfloat16(v.w - __bfloat162float(h3));
    ((__nv_bfloat162*)hi)[i * 2 + 0] = __nv_bfloat162(h0, h1);
    ((__nv_bfloat162*)hi)[i * 2 + 1] = __nv_bfloat162(h2, h3);
    ((__nv_bfloat162*)lo)[i * 2 + 0] = __nv_bfloat162(l0, l1);
    ((__nv_bfloat162*)lo)[i * 2 + 1] = __nv_bfloat162(l2, l3);
}

// ---------------- mma.sync split-bf16 GEMM ----------------
// C[m,n] = sum_k A[m,k]*B[n,k] + bias[n]  via Ah*Bh + Ah*Bl + Al*Bh
// CTA tile 128x128, KC=32, 8 warps (2x4), warp tile 64x32, double-buffered cp.async.
#define KC 32
#define LDT 40                      // padded smem row stride in bf16 (80 bytes)
#define TILE_E (128*LDT)            // elements per tile buffer
#define STAGE_E (4*TILE_E)          // Ah, Al, Bh, Bl

__global__ __launch_bounds__(256)
void mma_gemm_kernel(const __nv_bfloat16* __restrict__ Ah, const __nv_bfloat16* __restrict__ Al,
                     const __nv_bfloat16* __restrict__ Bh, const __nv_bfloat16* __restrict__ Bl,
                     const float* __restrict__ bias, float* __restrict__ C,
                     int M, int N, int K)
{
    extern __shared__ __nv_bfloat16 sm[];
    int tid = threadIdx.x;
    int lane = tid & 31, wid = tid >> 5;
    int wm = wid & 1, wn = wid >> 1;           // warp 64-row, 32-col tile
    int m0 = blockIdx.y * 128, n0 = blockIdx.x * 128;
    int NC = K / KC;
    uint32_t sb = smem_u32(sm);

    float acc[4][4][4];
#pragma unroll
    for (int mt = 0; mt < 4; mt++)
#pragma unroll
        for (int nt = 0; nt < 4; nt++)
#pragma unroll
            for (int r = 0; r < 4; r++) acc[mt][nt][r] = 0.0f;

    // issue cp.async loads of k-chunk kc into stage stg
    auto issue = [&](int kc, int stg) {
#pragma unroll
        for (int i = 0; i < 8; i++) {
            int c = tid + (i << 8);
            int tile = c >> 9;               // 0=Ah 1=Al 2=Bh 3=Bl
            int r = (c >> 2) & 127;
            int q = c & 3;
            uint32_t sa = sb + (uint32_t)(stg * STAGE_E + tile * TILE_E + r * LDT) * 2
                             + (uint32_t)q * 16;
            const __nv_bfloat16* g;
            if (tile == 0)      g = Ah + (size_t)(m0 + r) * K;
            else if (tile == 1) g = Al + (size_t)(m0 + r) * K;
            else if (tile == 2) g = Bh + (size_t)(n0 + r) * K;
            else                g = Bl + (size_t)(n0 + r) * K;
            g += kc * KC + q * 8;
            asm volatile("cp.async.cg.shared.global [%0], [%1], 16;" :: "r"(sa), "l"(g));
        }
        asm volatile("cp.async.commit_group;" ::: "memory");
    };

    issue(0, 0);

    for (int kc = 0; kc < NC; kc++) {
        int stg = kc & 1;
        if (kc + 1 < NC) issue(kc + 1, (kc + 1) & 1);
        if (kc + 1 < NC)
            asm volatile("cp.async.wait_group 1;" ::: "memory");
        else
            asm volatile("cp.async.wait_group 0;" ::: "memory");
        __syncthreads();

        uint32_t abase = sb + (uint32_t)(stg * STAGE_E) * 2
                       + (uint32_t)((wm * 64 + (lane & 15)) * LDT + (lane >> 4) * 8) * 2;
        uint32_t bbase = sb + (uint32_t)(stg * STAGE_E + 2 * TILE_E) * 2
                       + (uint32_t)((wn * 32 + (lane & 15)) * LDT + (lane >> 4) * 8) * 2;

#pragma unroll
        for (int kt = 0; kt < 2; kt++) {
            uint32_t kb = (uint32_t)(kt * 16) * 2;
            uint32_t ah[4][4], al[4][4], bh[2][4], bl[2][4];
#pragma unroll
            for (int mt = 0; mt < 4; mt++) {
                uint32_t a = abase + (uint32_t)(mt * 16 * LDT) * 2 + kb;
                ldsm4(ah[mt], a);
                ldsm4(al[mt], a + (uint32_t)TILE_E * 2);
            }
#pragma unroll
            for (int nt2 = 0; nt2 < 2; nt2++) {
                uint32_t b = bbase + (uint32_t)(nt2 * 16 * LDT) * 2 + kb;
                ldsm4(bh[nt2], b);
                ldsm4(bl[nt2], b + (uint32_t)TILE_E * 2);
            }
#pragma unroll
            for (int mt = 0; mt < 4; mt++)
#pragma unroll
                for (int nt = 0; nt < 4; nt++) {
                    int n2 = nt >> 1, hf = nt & 1;
                    mma16816(acc[mt][nt], ah[mt], bh[n2][hf], bh[n2][hf + 2]);
                    mma16816(acc[mt][nt], ah[mt], bl[n2][hf], bl[n2][hf + 2]);
                    mma16816(acc[mt][nt], al[mt], bh[n2][hf], bh[n2][hf + 2]);
                }
        }
        __syncthreads();
    }

    // epilogue
#pragma unroll
    for (int mt = 0; mt < 4; mt++) {
        int row = m0 + wm * 64 + mt * 16 + (lane >> 2);
#pragma unroll
        for (int nt = 0; nt < 4; nt++) {
            int col = n0 + wn * 32 + nt * 8 + (lane & 3) * 2;
            float b0 = bias[col], b1 = bias[col + 1];
            float2* p0 = (float2*)&C[(size_t)row * N + col];
            float2* p1 = (float2*)&C[(size_t)(row + 8) * N + col];
            *p0 = make_float2(acc[mt][nt][0] + b0, acc[mt][nt][1] + b1);
            *p1 = make_float2(acc[mt][nt][2] + b0, acc[mt][nt][3] + b1);
        }
    }
}

// ---------------- RoPE cos/sin table ----------------
__global__ void rope_table_kernel() {
    int idx = blockIdx.x * blockDim.x + threadIdx.x;
    if (idx >= Sm * DHm) return;
    int s = idx >> 6, d = idx & 63, i = d & 31;
    double inv = pow(10000.0, -(double)(2 * i) / 64.0);
    double ang = fmod((double)s * inv, 6.283185307179586476925287);
    double sn, cs;
    sincos(ang, &sn, &cs);
    g_cos[idx] = (float)cs;
    g_sin[idx] = (float)sn;
}

// ---------------- RoPE apply + transpose to [B,H,S,Dh] ----------------
__global__ void rope_apply_kernel() {
    int idx = blockIdx.x * blockDim.x + threadIdx.x;
    int d = idx & 63;
    int h = (idx >> 6) & 15;
    int s = (idx >> 10) & 2047;
    int b = idx >> 21;
    int base = (b * Sm + s) * QKVN + h * DHm;
    float c  = g_cos[(s << 6) + d];
    float sn = g_sin[(s << 6) + d];
    int dp = d ^ 32;
    float sgn = (d < 32) ? -1.0f : 1.0f;
    float q  = g_qkv[base + d];
    float qp = g_qkv[base + dp];
    float k  = g_qkv[base + Dm + d];
    float kp = g_qkv[base + Dm + dp];
    int o = ((b * Hm + h) * Sm + s) * DHm + d;
    g_q[o] = fmaf(q, c, sgn * qp * sn);
    g_k[o] = fmaf(k, c, sgn * kp * sn);
}

// ---------------- Flash attention (causal), 64x64 tiles, fp32 ----------------
#define TP 68

__global__ __launch_bounds__(256)
void attn_kernel() {
    extern __shared__ float smf[];
    float* Qs  = smf;
    float* Kst = smf + 64 * TP;
    float* Vs  = smf + 2 * 64 * TP;
    float* Ps  = smf + 3 * 64 * TP;

    int tid = threadIdx.x;
    int tx = tid & 15, ty = tid >> 4;
    int bh = blockIdx.y;
    int b = bh >> 4, h = bh & 15;
    int i0 = blockIdx.x * 64;
    const float scale = 0.125f;

    for (int it = tid; it < 1024; it += 256) {
        int r = it >> 4, c4 = (it & 15) << 2;
        float4 v = *(const float4*)&g_q[((size_t)bh * Sm + i0 + r) * DHm + c4];
        *(float4*)&Qs[r * TP + c4] = v;
    }

    float m[4], l[4], o[4][4];
#pragma unroll
    for (int i = 0; i < 4; i++) {
        m[i] = -INFINITY; l[i] = 0.0f;
#pragma unroll
        for (int j = 0; j < 4; j++) o[i][j] = 0.0f;
    }

    for (int j0 = 0; j0 <= i0; j0 += 64) {
        __syncthreads();
        for (int it = tid; it < 1024; it += 256) {
            int r = it >> 4, c4 = (it & 15) << 2;
            float4 kv = *(const float4*)&g_k[((size_t)bh * Sm + j0 + r) * DHm + c4];
            Kst[(c4 + 0) * TP + r] = kv.x;
            Kst[(c4 + 1) * TP + r] = kv.y;
            Kst[(c4 + 2) * TP + r] = kv.z;
            Kst[(c4 + 3) * TP + r] = kv.w;
            float4 vv = *(const float4*)&g_qkv[(size_t)(b * Sm + j0 + r) * QKVN
                                               + 2 * Dm + h * DHm + c4];
            *(float4*)&Vs[r * TP + c4] = vv;
        }
        __syncthreads();

        float sacc[4][4];
#pragma unroll
        for (int i = 0; i < 4; i++)
#pragma unroll
            for (int j = 0; j < 4; j++) sacc[i][j] = 0.0f;

#pragma unroll 4
        for (int kk = 0; kk < 64; kk++) {
            float4 kf = *(float4*)&Kst[kk * TP + tx * 4];
            float kr[4] = {kf.x, kf.y, kf.z, kf.w};
            float qr[4];
#pragma unroll
            for (int i = 0; i < 4; i++) qr[i] = Qs[(ty * 4 + i) * TP + kk];
#pragma unroll
            for (int i = 0; i < 4; i++)
#pragma unroll
                for (int j = 0; j < 4; j++)
                    sacc[i][j] = fmaf(qr[i], kr[j], sacc[i][j]);
        }

        bool diag = (j0 == i0);
#pragma unroll
        for (int i = 0; i < 4; i++) {
            int r = ty * 4 + i;
            float p[4];
#pragma unroll
            for (int j = 0; j < 4; j++) {
                float sv = sacc[i][j] * scale;
                if (diag && (tx * 4 + j) > r) sv = -INFINITY;
                p[j] = sv;
            }
            float mt = fmaxf(fmaxf(p[0], p[1]), fmaxf(p[2], p[3]));
            mt = fmaxf(mt, __shfl_xor_sync(0xffffffffu, mt, 8));
            mt = fmaxf(mt, __shfl_xor_sync(0xffffffffu, mt, 4));
            mt = fmaxf(mt, __shfl_xor_sync(0xffffffffu, mt, 2));
            mt = fmaxf(mt, __shfl_xor_sync(0xffffffffu, mt, 1));
            float mnew  = fmaxf(m[i], mt);
            float alpha = __expf(m[i] - mnew);
            float rs = 0.0f;
#pragma unroll
            for (int j = 0; j < 4; j++) { p[j] = __expf(p[j] - mnew); rs += p[j]; }
            rs += __shfl_xor_sync(0xffffffffu, rs, 8);
            rs += __shfl_xor_sync(0xffffffffu, rs, 4);
            rs += __shfl_xor_sync(0xffffffffu, rs, 2);
            rs += __shfl_xor_sync(0xffffffffu, rs, 1);
            l[i] = l[i] * alpha + rs;
            m[i] = mnew;
#pragma unroll
            for (int j = 0; j < 4; j++) o[i][j] *= alpha;
            *(float4*)&Ps[r * TP + tx * 4] = make_float4(p[0], p[1], p[2], p[3]);
        }
        __syncthreads();

#pragma unroll 4
        for (int c = 0; c < 64; c++) {
            float4 vf = *(float4*)&Vs[c * TP + tx * 4];
            float vr[4] = {vf.x, vf.y, vf.z, vf.w};
            float pr[4];
#pragma unroll
            for (int i = 0; i < 4; i++) pr[i] = Ps[(ty * 4 + i) * TP + c];
#pragma unroll
            for (int i = 0; i < 4; i++)
#pragma unroll
                for (int j = 0; j < 4; j++)
                    o[i][j] = fmaf(pr[i], vr[j], o[i][j]);
        }
    }

#pragma unroll
    for (int i = 0; i < 4; i++) {
        float invl = 1.0f / l[i];
        float4 ov = make_float4(o[i][0] * invl, o[i][1] * invl,
                                o[i][2] * invl, o[i][3] * invl);
        *(float4*)&g_ctx[(size_t)(b * Sm + i0 + ty * 4 + i) * Dm + h * DHm + tx * 4] = ov;
    }
}

// ---------------- launch ----------------
extern "C" void kernel_launch(void* const* d_in, const int* in_sizes, int n_in,
                              void* d_out, int out_size)
{
    const float* x      = (const float*)d_in[0];
    const float* qkv_w  = (const float*)d_in[1];
    const float* qkv_b  = (const float*)d_in[2];
    const float* proj_w = (const float*)d_in[3];
    const float* proj_b = (const float*)d_in[4];
    float* out = (float*)d_out;

    float *p_qkv, *p_ctx;
    cudaGetSymbolAddress((void**)&p_qkv, g_qkv);
    cudaGetSymbolAddress((void**)&p_ctx, g_ctx);
    __nv_bfloat16 *p_xh, *p_xl, *p_wh, *p_wl, *p_ch, *p_cl, *p_ph, *p_pl;
    cudaGetSymbolAddress((void**)&p_xh, g_xh);
    cudaGetSymbolAddress((void**)&p_xl, g_xl);
    cudaGetSymbolAddress((void**)&p_wh, g_wh);
    cudaGetSymbolAddress((void**)&p_wl, g_wl);
    cudaGetSymbolAddress((void**)&p_ch, g_ch);
    cudaGetSymbolAddress((void**)&p_cl, g_cl);
    cudaGetSymbolAddress((void**)&p_ph, g_ph);
    cudaGetSymbolAddress((void**)&p_pl, g_pl);

    int smem_attn = 4 * 64 * TP * sizeof(float);
    cudaFuncSetAttribute(attn_kernel, cudaFuncAttributeMaxDynamicSharedMemorySize, smem_attn);
    int smem_gemm = 2 * STAGE_E * sizeof(__nv_bfloat16);   // 81920
    cudaFuncSetAttribute(mma_gemm_kernel, cudaFuncAttributeMaxDynamicSharedMemorySize, smem_gemm);

    // 1) split x and qkv_w to bf16 hi/lo
    split_kernel<<<(MROWS * Dm / 4 + 255) / 256, 256>>>(x, p_xh, p_xl, MROWS * Dm / 4);
    split_kernel<<<(QKVN * Dm / 4 + 255) / 256, 256>>>(qkv_w, p_wh, p_wl, QKVN * Dm / 4);

    // 2) QKV GEMM (mma.sync split bf16)
    mma_gemm_kernel<<<dim3(QKVN / 128, MROWS / 128), 256, smem_gemm>>>(
        p_xh, p_xl, p_wh, p_wl, qkv_b, p_qkv, MROWS, QKVN, Dm);

    // 3) RoPE
    rope_table_kernel<<<(Sm * DHm + 255) / 256, 256>>>();
    rope_apply_kernel<<<(Bm * Sm * Hm * DHm) / 256, 256>>>();

    // 4) causal flash attention (fp32) -> g_ctx
    attn_kernel<<<dim3(Sm / 64, Bm * Hm), 256, smem_attn>>>();

    // 5) split ctx and proj_w; proj GEMM
    split_kernel<<<(MROWS * Dm / 4 + 255) / 256, 256>>>(p_ctx, p_ch, p_cl, MROWS * Dm / 4);
    split_kernel<<<(Dm * Dm / 4 + 255) / 256, 256>>>(proj_w, p_ph, p_pl, Dm * Dm / 4);
    mma_gemm_kernel<<<dim3(Dm / 128, MROWS / 128), 256, smem_gemm>>>(
        p_ch, p_cl, p_ph, p_pl, proj_b, out, MROWS, Dm, Dm);
}

// round 7
// speedup vs baseline: 2.6565x; 1.6800x over previous
#include <cuda_runtime.h>
#include <cuda_bf16.h>
#include <math.h>
#include <stdint.h>

#define Bm   2
#define Sm   2048
#define Dm   1024
#define Hm   16
#define DHm  64
#define MROWS (Bm*Sm)      // 4096
#define QKVN  (3*Dm)       // 3072

// ---------------- scratch (device globals; no allocation) ----------------
__device__ float g_qkv[MROWS * QKVN];     // [B*S, 3072] (q|k|v per head)
__device__ float g_cos[Sm * DHm];
__device__ float g_sin[Sm * DHm];

// bf16 split buffers
__device__ __nv_bfloat16 g_xh [MROWS * Dm];
__device__ __nv_bfloat16 g_xl [MROWS * Dm];
__device__ __nv_bfloat16 g_wh [QKVN * Dm];
__device__ __nv_bfloat16 g_wl [QKVN * Dm];
__device__ __nv_bfloat16 g_ph [Dm * Dm];
__device__ __nv_bfloat16 g_pl [Dm * Dm];
// rope'd q/k and v, [B,H,S,Dh], bf16 hi/lo
__device__ __nv_bfloat16 g_qh [Bm*Hm*Sm*DHm];
__device__ __nv_bfloat16 g_ql [Bm*Hm*Sm*DHm];
__device__ __nv_bfloat16 g_kh [Bm*Hm*Sm*DHm];
__device__ __nv_bfloat16 g_kl [Bm*Hm*Sm*DHm];
__device__ __nv_bfloat16 g_vh [Bm*Hm*Sm*DHm];
__device__ __nv_bfloat16 g_vl [Bm*Hm*Sm*DHm];
// attention context, bf16 hi/lo [B*S, D]
__device__ __nv_bfloat16 g_ch [MROWS * Dm];
__device__ __nv_bfloat16 g_cl [MROWS * Dm];

// ---------------- helpers ----------------
__device__ __forceinline__ uint32_t smem_u32(const void* p) {
    uint32_t a;
    asm("{ .reg .u64 t; cvta.to.shared.u64 t, %1; cvt.u32.u64 %0, t; }" : "=r"(a) : "l"(p));
    return a;
}
__device__ __forceinline__ void ldsm4(uint32_t* r, uint32_t addr) {
    asm volatile("ldmatrix.sync.aligned.m8n8.x4.shared.b16 {%0,%1,%2,%3}, [%4];"
                 : "=r"(r[0]), "=r"(r[1]), "=r"(r[2]), "=r"(r[3]) : "r"(addr));
}
__device__ __forceinline__ void ldsm4t(uint32_t* r, uint32_t addr) {
    asm volatile("ldmatrix.sync.aligned.m8n8.x4.trans.shared.b16 {%0,%1,%2,%3}, [%4];"
                 : "=r"(r[0]), "=r"(r[1]), "=r"(r[2]), "=r"(r[3]) : "r"(addr));
}
__device__ __forceinline__ void mma16816(float* c, const uint32_t* a, uint32_t b0, uint32_t b1) {
    asm volatile("mma.sync.aligned.m16n8k16.row.col.f32.bf16.bf16.f32 "
                 "{%0,%1,%2,%3}, {%4,%5,%6,%7}, {%8,%9}, {%0,%1,%2,%3};"
                 : "+f"(c[0]), "+f"(c[1]), "+f"(c[2]), "+f"(c[3])
                 : "r"(a[0]), "r"(a[1]), "r"(a[2]), "r"(a[3]), "r"(b0), "r"(b1));
}
__device__ __forceinline__ uint32_t packbf(float lo, float hi) {
    __nv_bfloat162 v = __floats2bfloat162_rn(lo, hi);
    return *(uint32_t*)&v;
}

// ---------------- split conversion ----------------
__global__ void split_kernel(const float* __restrict__ src, __nv_bfloat16* __restrict__ hi,
                             __nv_bfloat16* __restrict__ lo, int n4) {
    int i = blockIdx.x * blockDim.x + threadIdx.x;
    if (i >= n4) return;
    float4 v = ((const float4*)src)[i];
    __nv_bfloat16 h0 = __float2bfloat16(v.x), h1 = __float2bfloat16(v.y);
    __nv_bfloat16 h2 = __float2bfloat16(v.z), h3 = __float2bfloat16(v.w);
    __nv_bfloat16 l0 = __float2bfloat16(v.x - __bfloat162float(h0));
    __nv_bfloat16 l1 = __float2bfloat16(v.y - __bfloat162float(h1));
    __nv_bfloat16 l2 = __float2bfloat16(v.z - __bfloat162float(h2));
    __nv_bfloat16 l3 = __float2bfloat16(v.w - __bfloat162float(h3));
    ((__nv_bfloat162*)hi)[i * 2 + 0] = __nv_bfloat162(h0, h1);
    ((__nv_bfloat162*)hi)[i * 2 + 1] = __nv_bfloat162(h2, h3);
    ((__nv_bfloat162*)lo)[i * 2 + 0] = __nv_bfloat162(l0, l1);
    ((__nv_bfloat162*)lo)[i * 2 + 1] = __nv_bfloat162(l2, l3);
}

// ---------------- mma.sync split-bf16 GEMM (same as R3) ----------------
#define KC 32
#define LDT 40
#define TILE_E (128*LDT)
#define STAGE_E (4*TILE_E)

__global__ __launch_bounds__(256)
void mma_gemm_kernel(const __nv_bfloat16* __restrict__ Ah, const __nv_bfloat16* __restrict__ Al,
                     const __nv_bfloat16* __restrict__ Bh, const __nv_bfloat16* __restrict__ Bl,
                     const float* __restrict__ bias, float* __restrict__ C,
                     int M, int N, int K)
{
    extern __shared__ __nv_bfloat16 sm[];
    int tid = threadIdx.x;
    int lane = tid & 31, wid = tid >> 5;
    int wm = wid & 1, wn = wid >> 1;
    int m0 = blockIdx.y * 128, n0 = blockIdx.x * 128;
    int NC = K / KC;
    uint32_t sb = smem_u32(sm);

    float acc[4][4][4];
#pragma unroll
    for (int mt = 0; mt < 4; mt++)
#pragma unroll
        for (int nt = 0; nt < 4; nt++)
#pragma unroll
            for (int r = 0; r < 4; r++) acc[mt][nt][r] = 0.0f;

    auto issue = [&](int kc, int stg) {
#pragma unroll
        for (int i = 0; i < 8; i++) {
            int c = tid + (i << 8);
            int tile = c >> 9;
            int r = (c >> 2) & 127;
            int q = c & 3;
            uint32_t sa = sb + (uint32_t)(stg * STAGE_E + tile * TILE_E + r * LDT) * 2
                             + (uint32_t)q * 16;
            const __nv_bfloat16* g;
            if (tile == 0)      g = Ah + (size_t)(m0 + r) * K;
            else if (tile == 1) g = Al + (size_t)(m0 + r) * K;
            else if (tile == 2) g = Bh + (size_t)(n0 + r) * K;
            else                g = Bl + (size_t)(n0 + r) * K;
            g += kc * KC + q * 8;
            asm volatile("cp.async.cg.shared.global [%0], [%1], 16;" :: "r"(sa), "l"(g));
        }
        asm volatile("cp.async.commit_group;" ::: "memory");
    };

    issue(0, 0);

    for (int kc = 0; kc < NC; kc++) {
        int stg = kc & 1;
        if (kc + 1 < NC) issue(kc + 1, (kc + 1) & 1);
        if (kc + 1 < NC)
            asm volatile("cp.async.wait_group 1;" ::: "memory");
        else
            asm volatile("cp.async.wait_group 0;" ::: "memory");
        __syncthreads();

        uint32_t abase = sb + (uint32_t)(stg * STAGE_E) * 2
                       + (uint32_t)((wm * 64 + (lane & 15)) * LDT + (lane >> 4) * 8) * 2;
        uint32_t bbase = sb + (uint32_t)(stg * STAGE_E + 2 * TILE_E) * 2
                       + (uint32_t)((wn * 32 + (lane & 15)) * LDT + (lane >> 4) * 8) * 2;

#pragma unroll
        for (int kt = 0; kt < 2; kt++) {
            uint32_t kb = (uint32_t)(kt * 16) * 2;
            uint32_t ah[4][4], al[4][4], bh[2][4], bl[2][4];
#pragma unroll
            for (int mt = 0; mt < 4; mt++) {
                uint32_t a = abase + (uint32_t)(mt * 16 * LDT) * 2 + kb;
                ldsm4(ah[mt], a);
                ldsm4(al[mt], a + (uint32_t)TILE_E * 2);
            }
#pragma unroll
            for (int nt2 = 0; nt2 < 2; nt2++) {
                uint32_t b = bbase + (uint32_t)(nt2 * 16 * LDT) * 2 + kb;
                ldsm4(bh[nt2], b);
                ldsm4(bl[nt2], b + (uint32_t)TILE_E * 2);
            }
#pragma unroll
            for (int mt = 0; mt < 4; mt++)
#pragma unroll
                for (int nt = 0; nt < 4; nt++) {
                    int n2 = nt >> 1, hf = nt & 1;
                    mma16816(acc[mt][nt], ah[mt], bh[n2][hf], bh[n2][hf + 2]);
                    mma16816(acc[mt][nt], ah[mt], bl[n2][hf], bl[n2][hf + 2]);
                    mma16816(acc[mt][nt], al[mt], bh[n2][hf], bh[n2][hf + 2]);
                }
        }
        __syncthreads();
    }

#pragma unroll
    for (int mt = 0; mt < 4; mt++) {
        int row = m0 + wm * 64 + mt * 16 + (lane >> 2);
#pragma unroll
        for (int nt = 0; nt < 4; nt++) {
            int col = n0 + wn * 32 + nt * 8 + (lane & 3) * 2;
            float b0 = bias[col], b1 = bias[col + 1];
            float2* p0 = (float2*)&C[(size_t)row * N + col];
            float2* p1 = (float2*)&C[(size_t)(row + 8) * N + col];
            *p0 = make_float2(acc[mt][nt][0] + b0, acc[mt][nt][1] + b1);
            *p1 = make_float2(acc[mt][nt][2] + b0, acc[mt][nt][3] + b1);
        }
    }
}

// ---------------- RoPE cos/sin table ----------------
__global__ void rope_table_kernel() {
    int idx = blockIdx.x * blockDim.x + threadIdx.x;
    if (idx >= Sm * DHm) return;
    int s = idx >> 6, d = idx & 63, i = d & 31;
    double inv = pow(10000.0, -(double)(2 * i) / 64.0);
    double ang = fmod((double)s * inv, 6.283185307179586476925287);
    float sn, cs;
    sincosf((float)ang, &sn, &cs);
    g_cos[idx] = cs;
    g_sin[idx] = sn;
}

// ---------------- fused RoPE + split -> bf16 q/k/v in [B,H,S,Dh] ----------------
__global__ void rope_split_kernel() {
    int idx = blockIdx.x * blockDim.x + threadIdx.x;
    int d = idx & 63;
    int h = (idx >> 6) & 15;
    int s = (idx >> 10) & 2047;
    int b = idx >> 21;
    int base = (b * Sm + s) * QKVN + h * DHm;
    float c  = g_cos[(s << 6) + d];
    float sn = g_sin[(s << 6) + d];
    int dp = d ^ 32;
    float sgn = (d < 32) ? -1.0f : 1.0f;
    float q  = g_qkv[base + d];
    float qp = g_qkv[base + dp];
    float k  = g_qkv[base + Dm + d];
    float kp = g_qkv[base + Dm + dp];
    float v  = g_qkv[base + 2 * Dm + d];
    float qr = fmaf(q, c, sgn * qp * sn);
    float kr = fmaf(k, c, sgn * kp * sn);
    int o = ((b * Hm + h) * Sm + s) * DHm + d;
    __nv_bfloat16 qh = __float2bfloat16(qr);
    __nv_bfloat16 kh = __float2bfloat16(kr);
    __nv_bfloat16 vh = __float2bfloat16(v);
    g_qh[o] = qh; g_ql[o] = __float2bfloat16(qr - __bfloat162float(qh));
    g_kh[o] = kh; g_kl[o] = __float2bfloat16(kr - __bfloat162float(kh));
    g_vh[o] = vh; g_vl[o] = __float2bfloat16(v  - __bfloat162float(vh));
}

// ---------------- flash attention on mma.sync (causal, split bf16) ----------------
// 128 Q rows per CTA, 8 warps x 16 rows, 64-col K/V tiles, double-buffered cp.async.
#define LDK 72
#define QSZ (128*LDK)
#define KSZ (64*LDK)
#define STG (4*KSZ)

__global__ __launch_bounds__(256, 2)
void attn_mma_kernel() {
    extern __shared__ __nv_bfloat16 asm_[];
    uint32_t sb = smem_u32(asm_);
    int tid = threadIdx.x;
    int lane = tid & 31, w = tid >> 5;
    int bh = blockIdx.y;
    int bidx = bh >> 4, hidx = bh & 15;
    int i0 = blockIdx.x * 128;
    int wr0 = w * 16;
    int ntiles = 2 * blockIdx.x + 2;
    const float SC = 0.125f;

    // issue K/V tile jt into stage stg
    auto issue_kv = [&](int jt, int stg) {
        int j0 = jt * 64;
#pragma unroll
        for (int i = 0; i < 8; i++) {
            int c = tid + (i << 8);
            int tile = c >> 9;
            int r = (c >> 3) & 63;
            int q = c & 7;
            uint32_t sa = sb + (uint32_t)(2 * QSZ + stg * STG + tile * KSZ + r * LDK + q * 8) * 2;
            const __nv_bfloat16* g;
            if (tile == 0)      g = g_kh;
            else if (tile == 1) g = g_kl;
            else if (tile == 2) g = g_vh;
            else                g = g_vl;
            g += ((size_t)bh * Sm + j0 + r) * DHm + q * 8;
            asm volatile("cp.async.cg.shared.global [%0], [%1], 16;" :: "r"(sa), "l"(g));
        }
        asm volatile("cp.async.commit_group;" ::: "memory");
    };

    // Q loads (hi+lo): 2048 chunks
#pragma unroll
    for (int i = 0; i < 8; i++) {
        int c = tid + (i << 8);
        int half = c >> 10;
        int cc = c & 1023;
        int r = cc >> 3, q = cc & 7;
        uint32_t sa = sb + (uint32_t)(half * QSZ + r * LDK + q * 8) * 2;
        const __nv_bfloat16* g = (half ? g_ql : g_qh)
                               + ((size_t)bh * Sm + i0 + r) * DHm + q * 8;
        asm volatile("cp.async.cg.shared.global [%0], [%1], 16;" :: "r"(sa), "l"(g));
    }
    issue_kv(0, 0);
    asm volatile("cp.async.commit_group;" ::: "memory");

    float O[8][4];
#pragma unroll
    for (int nt = 0; nt < 8; nt++)
#pragma unroll
        for (int r = 0; r < 4; r++) O[nt][r] = 0.0f;
    float m_lo = -1e30f, m_hi = -1e30f, l_lo = 0.0f, l_hi = 0.0f;

    int gi_lo = i0 + wr0 + (lane >> 2);
    int gi_hi = gi_lo + 8;
    int colb = (lane & 3) << 1;

    for (int jt = 0; jt < ntiles; jt++) {
        int stg = jt & 1;
        int j0 = jt * 64;
        if (jt + 1 < ntiles) issue_kv(jt + 1, (jt + 1) & 1);
        if (jt + 1 < ntiles)
            asm volatile("cp.async.wait_group 1;" ::: "memory");
        else
            asm volatile("cp.async.wait_group 0;" ::: "memory");
        __syncthreads();

        bool skip = (j0 > i0 + wr0 + 15);
        if (!skip) {
            uint32_t SB2 = 2 * QSZ + stg * STG;
            // ---- S = Q K^T ----
            float c[8][4];
#pragma unroll
            for (int nt = 0; nt < 8; nt++)
#pragma unroll
                for (int r = 0; r < 4; r++) c[nt][r] = 0.0f;

            uint32_t qoffe = (uint32_t)((wr0 + (lane & 15)) * LDK + (lane >> 4) * 8);
            uint32_t koffe = (uint32_t)(((lane & 15)) * LDK + (lane >> 4) * 8);
#pragma unroll
            for (int kc = 0; kc < 4; kc++) {
                uint32_t qa = sb + (qoffe + kc * 16) * 2;
                uint32_t qah[4], qal[4];
                ldsm4(qah, qa);
                ldsm4(qal, qa + QSZ * 2);
#pragma unroll
                for (int np = 0; np < 4; np++) {
                    uint32_t ka = sb + (SB2 + np * 16 * LDK + koffe + kc * 16) * 2;
                    uint32_t kbh[4], kbl[4];
                    ldsm4(kbh, ka);
                    ldsm4(kbl, ka + KSZ * 2);
                    mma16816(c[2*np],   qah, kbh[0], kbh[2]);
                    mma16816(c[2*np],   qah, kbl[0], kbl[2]);
                    mma16816(c[2*np],   qal, kbh[0], kbh[2]);
                    mma16816(c[2*np+1], qah, kbh[1], kbh[3]);
                    mma16816(c[2*np+1], qah, kbl[1], kbl[3]);
                    mma16816(c[2*np+1], qal, kbh[1], kbh[3]);
                }
            }

            // ---- softmax ----
            bool needmask = (j0 + 63) > (i0 + wr0);
            float mxlo = -1e30f, mxhi = -1e30f;
#pragma unroll
            for (int nt = 0; nt < 8; nt++) {
                float s0 = c[nt][0] * SC, s1 = c[nt][1] * SC;
                float s2 = c[nt][2] * SC, s3 = c[nt][3] * SC;
                if (needmask) {
                    int j = j0 + nt * 8 + colb;
                    if (j     > gi_lo) s0 = -1e30f;
                    if (j + 1 > gi_lo) s1 = -1e30f;
                    if (j     > gi_hi) s2 = -1e30f;
                    if (j + 1 > gi_hi) s3 = -1e30f;
                }
                c[nt][0] = s0; c[nt][1] = s1; c[nt][2] = s2; c[nt][3] = s3;
                mxlo = fmaxf(mxlo, fmaxf(s0, s1));
                mxhi = fmaxf(mxhi, fmaxf(s2, s3));
            }
            mxlo = fmaxf(mxlo, __shfl_xor_sync(0xffffffffu, mxlo, 1));
            mxlo = fmaxf(mxlo, __shfl_xor_sync(0xffffffffu, mxlo, 2));
            mxhi = fmaxf(mxhi, __shfl_xor_sync(0xffffffffu, mxhi, 1));
            mxhi = fmaxf(mxhi, __shfl_xor_sync(0xffffffffu, mxhi, 2));
            float mnlo = fmaxf(m_lo, mxlo), mnhi = fmaxf(m_hi, mxhi);
            float alo = __expf(m_lo - mnlo), ahi = __expf(m_hi - mnhi);
            float slo = 0.0f, shi = 0.0f;
#pragma unroll
            for (int nt = 0; nt < 8; nt++) {
                float p0 = __expf(c[nt][0] - mnlo);
                float p1 = __expf(c[nt][1] - mnlo);
                float p2 = __expf(c[nt][2] - mnhi);
                float p3 = __expf(c[nt][3] - mnhi);
                c[nt][0] = p0; c[nt][1] = p1; c[nt][2] = p2; c[nt][3] = p3;
                slo += p0 + p1; shi += p2 + p3;
            }
            slo += __shfl_xor_sync(0xffffffffu, slo, 1);
            slo += __shfl_xor_sync(0xffffffffu, slo, 2);
            shi += __shfl_xor_sync(0xffffffffu, shi, 1);
            shi += __shfl_xor_sync(0xffffffffu, shi, 2);
            l_lo = l_lo * alo + slo; m_lo = mnlo;
            l_hi = l_hi * ahi + shi; m_hi = mnhi;
#pragma unroll
            for (int nt = 0; nt < 8; nt++) {
                O[nt][0] *= alo; O[nt][1] *= alo;
                O[nt][2] *= ahi; O[nt][3] *= ahi;
            }

            // ---- pack P hi/lo into A-fragments ----
            uint32_t pah[4][4], pal[4][4];
#pragma unroll
            for (int kc = 0; kc < 4; kc++) {
#pragma unroll
                for (int half = 0; half < 2; half++) {
                    int nt = 2 * kc + half;
                    float x0 = c[nt][0], x1 = c[nt][1];
                    float y0 = c[nt][2], y1 = c[nt][3];
                    __nv_bfloat16 hx0 = __float2bfloat16(x0), hx1 = __float2bfloat16(x1);
                    __nv_bfloat16 hy0 = __float2bfloat16(y0), hy1 = __float2bfloat16(y1);
                    pah[kc][half * 2 + 0] = packbf(__bfloat162float(hx0), __bfloat162float(hx1));
                    pah[kc][half * 2 + 1] = packbf(__bfloat162float(hy0), __bfloat162float(hy1));
                    pal[kc][half * 2 + 0] = packbf(x0 - __bfloat162float(hx0), x1 - __bfloat162float(hx1));
                    pal[kc][half * 2 + 1] = packbf(y0 - __bfloat162float(hy0), y1 - __bfloat162float(hy1));
                }
            }
            // fix ordering: a-frag = {a0(row,k0-7), a1(row+8,k0-7), a2(row,k8-15), a3(row+8,k8-15)}
            //   half=0 tile (cols 0-7) -> a0,a1 ; half=1 tile (cols 8-15) -> a2,a3  (matches above)

            // ---- O += P V ----
#pragma unroll
            for (int kc = 0; kc < 4; kc++) {
                uint32_t voffe = (uint32_t)(SB2 + 2 * KSZ + (kc * 16 + (lane & 15)) * LDK
                                            + (lane >> 4) * 8);
#pragma unroll
                for (int np = 0; np < 4; np++) {
                    uint32_t va = sb + (voffe + np * 16) * 2;
                    uint32_t vbh[4], vbl[4];
                    ldsm4t(vbh, va);
                    ldsm4t(vbl, va + KSZ * 2);
                    mma16816(O[2*np],   pah[kc], vbh[0], vbh[1]);
                    mma16816(O[2*np],   pah[kc], vbl[0], vbl[1]);
                    mma16816(O[2*np],   pal[kc], vbh[0], vbh[1]);
                    mma16816(O[2*np+1], pah[kc], vbh[2], vbh[3]);
                    mma16816(O[2*np+1], pah[kc], vbl[2], vbl[3]);
                    mma16816(O[2*np+1], pal[kc], vbh[2], vbh[3]);
                }
            }
        }
        __syncthreads();
    }

    // ---- normalize + store context as bf16 hi/lo ----
    float ivlo = 1.0f / l_lo, ivhi = 1.0f / l_hi;
    size_t rlo = (size_t)(bidx * Sm + gi_lo) * Dm;
    size_t rhi = (size_t)(bidx * Sm + gi_hi) * Dm;
#pragma unroll
    for (int nt = 0; nt < 8; nt++) {
        int col = hidx * DHm + nt * 8 + colb;
        float o0 = O[nt][0] * ivlo, o1 = O[nt][1] * ivlo;
        float o2 = O[nt][2] * ivhi, o3 = O[nt][3] * ivhi;
        __nv_bfloat16 h0 = __float2bfloat16(o0), h1 = __float2bfloat16(o1);
        __nv_bfloat16 h2 = __float2bfloat16(o2), h3 = __float2bfloat16(o3);
        *(uint32_t*)&g_ch[rlo + col] = packbf(__bfloat162float(h0), __bfloat162float(h1));
        *(uint32_t*)&g_ch[rhi + col] = packbf(__bfloat162float(h2), __bfloat162float(h3));
        *(uint32_t*)&g_cl[rlo + col] = packbf(o0 - __bfloat162float(h0), o1 - __bfloat162float(h1));
        *(uint32_t*)&g_cl[rhi + col] = packbf(o2 - __bfloat162float(h2), o3 - __bfloat162float(h3));
    }
}

// ---------------- launch ----------------
extern "C" void kernel_launch(void* const* d_in, const int* in_sizes, int n_in,
                              void* d_out, int out_size)
{
    const float* x      = (const float*)d_in[0];
    const float* qkv_w  = (const float*)d_in[1];
    const float* qkv_b  = (const float*)d_in[2];
    const float* proj_w = (const float*)d_in[3];
    const float* proj_b = (const float*)d_in[4];
    float* out = (float*)d_out;

    float* p_qkv;
    cudaGetSymbolAddress((void**)&p_qkv, g_qkv);
    __nv_bfloat16 *p_xh, *p_xl, *p_wh, *p_wl, *p_ch, *p_cl, *p_ph, *p_pl;
    cudaGetSymbolAddress((void**)&p_xh, g_xh);
    cudaGetSymbolAddress((void**)&p_xl, g_xl);
    cudaGetSymbolAddress((void**)&p_wh, g_wh);
    cudaGetSymbolAddress((void**)&p_wl, g_wl);
    cudaGetSymbolAddress((void**)&p_ch, g_ch);
    cudaGetSymbolAddress((void**)&p_cl, g_cl);
    cudaGetSymbolAddress((void**)&p_ph, g_ph);
    cudaGetSymbolAddress((void**)&p_pl, g_pl);

    int smem_gemm = 2 * STAGE_E * sizeof(__nv_bfloat16);
    cudaFuncSetAttribute(mma_gemm_kernel, cudaFuncAttributeMaxDynamicSharedMemorySize, smem_gemm);
    int smem_attn = (2 * QSZ + 2 * STG) * sizeof(__nv_bfloat16);   // 110592
    cudaFuncSetAttribute(attn_mma_kernel, cudaFuncAttributeMaxDynamicSharedMemorySize, smem_attn);

    // 1) split inputs
    split_kernel<<<(MROWS * Dm / 4 + 255) / 256, 256>>>(x, p_xh, p_xl, MROWS * Dm / 4);
    split_kernel<<<(QKVN * Dm / 4 + 255) / 256, 256>>>(qkv_w, p_wh, p_wl, QKVN * Dm / 4);

    // 2) QKV GEMM
    mma_gemm_kernel<<<dim3(QKVN / 128, MROWS / 128), 256, smem_gemm>>>(
        p_xh, p_xl, p_wh, p_wl, qkv_b, p_qkv, MROWS, QKVN, Dm);

    // 3) RoPE table + fused rope/split
    rope_table_kernel<<<(Sm * DHm + 255) / 256, 256>>>();
    rope_split_kernel<<<(Bm * Sm * Hm * DHm) / 256, 256>>>();

    // 4) flash attention (mma.sync, split bf16) -> g_ch/g_cl
    attn_mma_kernel<<<dim3(Sm / 128, Bm * Hm), 256, smem_attn>>>();

    // 5) proj GEMM
    split_kernel<<<(Dm * Dm / 4 + 255) / 256, 256>>>(proj_w, p_ph, p_pl, Dm * Dm / 4);
    mma_gemm_kernel<<<dim3(Dm / 128, MROWS / 128), 256, smem_gemm>>>(
        p_ch, p_cl, p_ph, p_pl, proj_b, out, MROWS, Dm, Dm);
}

// round 8
// speedup vs baseline: 2.7149x; 1.0220x over previous
#include <cuda_runtime.h>
#include <cuda_bf16.h>
#include <math.h>
#include <stdint.h>

#define Bm   2
#define Sm   2048
#define Dm   1024
#define Hm   16
#define DHm  64
#define MROWS (Bm*Sm)      // 4096
#define QKVN  (3*Dm)       // 3072

// ---------------- scratch (device globals; no allocation) ----------------
__device__ float g_qkv[MROWS * QKVN];     // [B*S, 3072] (q|k|v per head)
__device__ float g_cos[Sm * DHm];
__device__ float g_sin[Sm * DHm];
__device__ double g_inv[32];

// bf16 split buffers
__device__ __nv_bfloat16 g_xh [MROWS * Dm];
__device__ __nv_bfloat16 g_xl [MROWS * Dm];
__device__ __nv_bfloat16 g_wh [QKVN * Dm];
__device__ __nv_bfloat16 g_wl [QKVN * Dm];
__device__ __nv_bfloat16 g_ph [Dm * Dm];
__device__ __nv_bfloat16 g_pl [Dm * Dm];
// rope'd q/k and v, [B,H,S,Dh], bf16 hi/lo
__device__ __nv_bfloat16 g_qh [Bm*Hm*Sm*DHm];
__device__ __nv_bfloat16 g_ql [Bm*Hm*Sm*DHm];
__device__ __nv_bfloat16 g_kh [Bm*Hm*Sm*DHm];
__device__ __nv_bfloat16 g_kl [Bm*Hm*Sm*DHm];
__device__ __nv_bfloat16 g_vh [Bm*Hm*Sm*DHm];
__device__ __nv_bfloat16 g_vl [Bm*Hm*Sm*DHm];
// attention context, bf16 hi/lo [B*S, D]
__device__ __nv_bfloat16 g_ch [MROWS * Dm];
__device__ __nv_bfloat16 g_cl [MROWS * Dm];

// ---------------- helpers ----------------
__device__ __forceinline__ uint32_t smem_u32(const void* p) {
    uint32_t a;
    asm("{ .reg .u64 t; cvta.to.shared.u64 t, %1; cvt.u32.u64 %0, t; }" : "=r"(a) : "l"(p));
    return a;
}
__device__ __forceinline__ void ldsm4(uint32_t* r, uint32_t addr) {
    asm volatile("ldmatrix.sync.aligned.m8n8.x4.shared.b16 {%0,%1,%2,%3}, [%4];"
                 : "=r"(r[0]), "=r"(r[1]), "=r"(r[2]), "=r"(r[3]) : "r"(addr));
}
__device__ __forceinline__ void ldsm4t(uint32_t* r, uint32_t addr) {
    asm volatile("ldmatrix.sync.aligned.m8n8.x4.trans.shared.b16 {%0,%1,%2,%3}, [%4];"
                 : "=r"(r[0]), "=r"(r[1]), "=r"(r[2]), "=r"(r[3]) : "r"(addr));
}
__device__ __forceinline__ void mma16816(float* c, const uint32_t* a, uint32_t b0, uint32_t b1) {
    asm volatile("mma.sync.aligned.m16n8k16.row.col.f32.bf16.bf16.f32 "
                 "{%0,%1,%2,%3}, {%4,%5,%6,%7}, {%8,%9}, {%0,%1,%2,%3};"
                 : "+f"(c[0]), "+f"(c[1]), "+f"(c[2]), "+f"(c[3])
                 : "r"(a[0]), "r"(a[1]), "r"(a[2]), "r"(a[3]), "r"(b0), "r"(b1));
}
__device__ __forceinline__ uint32_t packbf(float lo, float hi) {
    __nv_bfloat162 v = __floats2bfloat162_rn(lo, hi);
    return *(uint32_t*)&v;
}

// ---------------- split conversion ----------------
__global__ void split_kernel(const float* __restrict__ src, __nv_bfloat16* __restrict__ hi,
                             __nv_bfloat16* __restrict__ lo, int n4) {
    int i = blockIdx.x * blockDim.x + threadIdx.x;
    if (i >= n4) return;
    float4 v = ((const float4*)src)[i];
    __nv_bfloat16 h0 = __float2bfloat16(v.x), h1 = __float2bfloat16(v.y);
    __nv_bfloat16 h2 = __float2bfloat16(v.z), h3 = __float2bfloat16(v.w);
    __nv_bfloat16 l0 = __float2bfloat16(v.x - __bfloat162float(h0));
    __nv_bfloat16 l1 = __float2bfloat16(v.y - __bfloat162float(h1));
    __nv_bfloat16 l2 = __float2bfloat16(v.z - __bfloat162float(h2));
    __nv_bfloat16 l3 = __float2bfloat16(v.w - __bfloat162float(h3));
    ((__nv_bfloat162*)hi)[i * 2 + 0] = __nv_bfloat162(h0, h1);
    ((__nv_bfloat162*)hi)[i * 2 + 1] = __nv_bfloat162(h2, h3);
    ((__nv_bfloat162*)lo)[i * 2 + 0] = __nv_bfloat162(l0, l1);
    ((__nv_bfloat162*)lo)[i * 2 + 1] = __nv_bfloat162(l2, l3);
}

// ---------------- mma.sync split-bf16 GEMM, KC=64 double-buffered ----------------
#define KC 64
#define LDT 72                      // padded smem row stride in bf16 (144 B)
#define TILE_E (128*LDT)            // 9216 elements per tile buffer
#define STAGE_E (4*TILE_E)          // Ah, Al, Bh, Bl

__global__ __launch_bounds__(256)
void mma_gemm_kernel(const __nv_bfloat16* __restrict__ Ah, const __nv_bfloat16* __restrict__ Al,
                     const __nv_bfloat16* __restrict__ Bh, const __nv_bfloat16* __restrict__ Bl,
                     const float* __restrict__ bias, float* __restrict__ C,
                     int M, int N, int K)
{
    extern __shared__ __nv_bfloat16 sm[];
    int tid = threadIdx.x;
    int lane = tid & 31, wid = tid >> 5;
    int wm = wid & 1, wn = wid >> 1;
    int m0 = blockIdx.y * 128, n0 = blockIdx.x * 128;
    int NC = K / KC;
    uint32_t sb = smem_u32(sm);

    float acc[4][4][4];
#pragma unroll
    for (int mt = 0; mt < 4; mt++)
#pragma unroll
        for (int nt = 0; nt < 4; nt++)
#pragma unroll
            for (int r = 0; r < 4; r++) acc[mt][nt][r] = 0.0f;

    // issue cp.async loads of k-chunk kc into stage stg: 4096 16B chunks, 16/thread
    auto issue = [&](int kc, int stg) {
#pragma unroll
        for (int i = 0; i < 16; i++) {
            int c = tid + (i << 8);
            int tile = c >> 10;              // 0=Ah 1=Al 2=Bh 3=Bl
            int r = (c >> 3) & 127;
            int q = c & 7;
            uint32_t sa = sb + (uint32_t)(stg * STAGE_E + tile * TILE_E + r * LDT + q * 8) * 2;
            const __nv_bfloat16* g;
            if (tile == 0)      g = Ah + (size_t)(m0 + r) * K;
            else if (tile == 1) g = Al + (size_t)(m0 + r) * K;
            else if (tile == 2) g = Bh + (size_t)(n0 + r) * K;
            else                g = Bl + (size_t)(n0 + r) * K;
            g += kc * KC + q * 8;
            asm volatile("cp.async.cg.shared.global [%0], [%1], 16;" :: "r"(sa), "l"(g));
        }
        asm volatile("cp.async.commit_group;" ::: "memory");
    };

    issue(0, 0);

    for (int kc = 0; kc < NC; kc++) {
        int stg = kc & 1;
        if (kc + 1 < NC) issue(kc + 1, (kc + 1) & 1);
        if (kc + 1 < NC)
            asm volatile("cp.async.wait_group 1;" ::: "memory");
        else
            asm volatile("cp.async.wait_group 0;" ::: "memory");
        __syncthreads();

        uint32_t abase = sb + (uint32_t)(stg * STAGE_E) * 2
                       + (uint32_t)((wm * 64 + (lane & 15)) * LDT + (lane >> 4) * 8) * 2;
        uint32_t bbase = sb + (uint32_t)(stg * STAGE_E + 2 * TILE_E) * 2
                       + (uint32_t)((wn * 32 + (lane & 15)) * LDT + (lane >> 4) * 8) * 2;

#pragma unroll
        for (int kt = 0; kt < 4; kt++) {
            uint32_t kb = (uint32_t)(kt * 16) * 2;
            uint32_t ah[4][4], al[4][4], bh[2][4], bl[2][4];
#pragma unroll
            for (int mt = 0; mt < 4; mt++) {
                uint32_t a = abase + (uint32_t)(mt * 16 * LDT) * 2 + kb;
                ldsm4(ah[mt], a);
                ldsm4(al[mt], a + (uint32_t)TILE_E * 2);
            }
#pragma unroll
            for (int nt2 = 0; nt2 < 2; nt2++) {
                uint32_t b = bbase + (uint32_t)(nt2 * 16 * LDT) * 2 + kb;
                ldsm4(bh[nt2], b);
                ldsm4(bl[nt2], b + (uint32_t)TILE_E * 2);
            }
#pragma unroll
            for (int mt = 0; mt < 4; mt++)
#pragma unroll
                for (int nt = 0; nt < 4; nt++) {
                    int n2 = nt >> 1, hf = nt & 1;
                    mma16816(acc[mt][nt], ah[mt], bh[n2][hf], bh[n2][hf + 2]);
                    mma16816(acc[mt][nt], ah[mt], bl[n2][hf], bl[n2][hf + 2]);
                    mma16816(acc[mt][nt], al[mt], bh[n2][hf], bh[n2][hf + 2]);
                }
        }
        __syncthreads();
    }

#pragma unroll
    for (int mt = 0; mt < 4; mt++) {
        int row = m0 + wm * 64 + mt * 16 + (lane >> 2);
#pragma unroll
        for (int nt = 0; nt < 4; nt++) {
            int col = n0 + wn * 32 + nt * 8 + (lane & 3) * 2;
            float b0 = bias[col], b1 = bias[col + 1];
            float2* p0 = (float2*)&C[(size_t)row * N + col];
            float2* p1 = (float2*)&C[(size_t)(row + 8) * N + col];
            *p0 = make_float2(acc[mt][nt][0] + b0, acc[mt][nt][1] + b1);
            *p1 = make_float2(acc[mt][nt][2] + b0, acc[mt][nt][3] + b1);
        }
    }
}

// ---------------- RoPE inv-freq (32 threads) + cos/sin table ----------------
__global__ void rope_freq_kernel() {
    int i = threadIdx.x;
    if (i < 32) g_inv[i] = pow(10000.0, -(double)(2 * i) / 64.0);
}
__global__ void rope_table_kernel() {
    int idx = blockIdx.x * blockDim.x + threadIdx.x;
    if (idx >= Sm * DHm) return;
    int s = idx >> 6, d = idx & 63, i = d & 31;
    double ang = fmod((double)s * g_inv[i], 6.283185307179586476925287);
    float sn, cs;
    sincosf((float)ang, &sn, &cs);
    g_cos[idx] = cs;
    g_sin[idx] = sn;
}

// ---------------- fused RoPE + split -> bf16 q/k/v in [B,H,S,Dh] ----------------
__global__ void rope_split_kernel() {
    int idx = blockIdx.x * blockDim.x + threadIdx.x;
    int d = idx & 63;
    int h = (idx >> 6) & 15;
    int s = (idx >> 10) & 2047;
    int b = idx >> 21;
    int base = (b * Sm + s) * QKVN + h * DHm;
    float c  = g_cos[(s << 6) + d];
    float sn = g_sin[(s << 6) + d];
    int dp = d ^ 32;
    float sgn = (d < 32) ? -1.0f : 1.0f;
    float q  = g_qkv[base + d];
    float qp = g_qkv[base + dp];
    float k  = g_qkv[base + Dm + d];
    float kp = g_qkv[base + Dm + dp];
    float v  = g_qkv[base + 2 * Dm + d];
    float qr = fmaf(q, c, sgn * qp * sn);
    float kr = fmaf(k, c, sgn * kp * sn);
    int o = ((b * Hm + h) * Sm + s) * DHm + d;
    __nv_bfloat16 qh = __float2bfloat16(qr);
    __nv_bfloat16 kh = __float2bfloat16(kr);
    __nv_bfloat16 vh = __float2bfloat16(v);
    g_qh[o] = qh; g_ql[o] = __float2bfloat16(qr - __bfloat162float(qh));
    g_kh[o] = kh; g_kl[o] = __float2bfloat16(kr - __bfloat162float(kh));
    g_vh[o] = vh; g_vl[o] = __float2bfloat16(v  - __bfloat162float(vh));
}

// ---------------- flash attention on mma.sync (causal, split bf16) ----------------
// 128 Q rows per CTA, 8 warps x 16 rows, 64-col K/V tiles, double-buffered cp.async.
#define LDK 72
#define QSZ (128*LDK)
#define KSZ (64*LDK)
#define STG (4*KSZ)

__global__ __launch_bounds__(256, 2)
void attn_mma_kernel() {
    extern __shared__ __nv_bfloat16 asm_[];
    uint32_t sb = smem_u32(asm_);
    int tid = threadIdx.x;
    int lane = tid & 31, w = tid >> 5;
    int bh = blockIdx.y;
    int bidx = bh >> 4, hidx = bh & 15;
    int i0 = blockIdx.x * 128;
    int wr0 = w * 16;
    int ntiles = 2 * blockIdx.x + 2;
    const float SC = 0.125f;

    auto issue_kv = [&](int jt, int stg) {
        int j0 = jt * 64;
#pragma unroll
        for (int i = 0; i < 8; i++) {
            int c = tid + (i << 8);
            int tile = c >> 9;
            int r = (c >> 3) & 63;
            int q = c & 7;
            uint32_t sa = sb + (uint32_t)(2 * QSZ + stg * STG + tile * KSZ + r * LDK + q * 8) * 2;
            const __nv_bfloat16* g;
            if (tile == 0)      g = g_kh;
            else if (tile == 1) g = g_kl;
            else if (tile == 2) g = g_vh;
            else                g = g_vl;
            g += ((size_t)bh * Sm + j0 + r) * DHm + q * 8;
            asm volatile("cp.async.cg.shared.global [%0], [%1], 16;" :: "r"(sa), "l"(g));
        }
        asm volatile("cp.async.commit_group;" ::: "memory");
    };

#pragma unroll
    for (int i = 0; i < 8; i++) {
        int c = tid + (i << 8);
        int half = c >> 10;
        int cc = c & 1023;
        int r = cc >> 3, q = cc & 7;
        uint32_t sa = sb + (uint32_t)(half * QSZ + r * LDK + q * 8) * 2;
        const __nv_bfloat16* g = (half ? g_ql : g_qh)
                               + ((size_t)bh * Sm + i0 + r) * DHm + q * 8;
        asm volatile("cp.async.cg.shared.global [%0], [%1], 16;" :: "r"(sa), "l"(g));
    }
    issue_kv(0, 0);
    asm volatile("cp.async.commit_group;" ::: "memory");

    float O[8][4];
#pragma unroll
    for (int nt = 0; nt < 8; nt++)
#pragma unroll
        for (int r = 0; r < 4; r++) O[nt][r] = 0.0f;
    float m_lo = -1e30f, m_hi = -1e30f, l_lo = 0.0f, l_hi = 0.0f;

    int gi_lo = i0 + wr0 + (lane >> 2);
    int gi_hi = gi_lo + 8;
    int colb = (lane & 3) << 1;

    for (int jt = 0; jt < ntiles; jt++) {
        int stg = jt & 1;
        int j0 = jt * 64;
        if (jt + 1 < ntiles) issue_kv(jt + 1, (jt + 1) & 1);
        if (jt + 1 < ntiles)
            asm volatile("cp.async.wait_group 1;" ::: "memory");
        else
            asm volatile("cp.async.wait_group 0;" ::: "memory");
        __syncthreads();

        bool skip = (j0 > i0 + wr0 + 15);
        if (!skip) {
            uint32_t SB2 = 2 * QSZ + stg * STG;
            float c[8][4];
#pragma unroll
            for (int nt = 0; nt < 8; nt++)
#pragma unroll
                for (int r = 0; r < 4; r++) c[nt][r] = 0.0f;

            uint32_t qoffe = (uint32_t)((wr0 + (lane & 15)) * LDK + (lane >> 4) * 8);
            uint32_t koffe = (uint32_t)(((lane & 15)) * LDK + (lane >> 4) * 8);
#pragma unroll
            for (int kc = 0; kc < 4; kc++) {
                uint32_t qa = sb + (qoffe + kc * 16) * 2;
                uint32_t qah[4], qal[4];
                ldsm4(qah, qa);
                ldsm4(qal, qa + QSZ * 2);
#pragma unroll
                for (int np = 0; np < 4; np++) {
                    uint32_t ka = sb + (SB2 + np * 16 * LDK + koffe + kc * 16) * 2;
                    uint32_t kbh[4], kbl[4];
                    ldsm4(kbh, ka);
                    ldsm4(kbl, ka + KSZ * 2);
                    mma16816(c[2*np],   qah, kbh[0], kbh[2]);
                    mma16816(c[2*np],   qah, kbl[0], kbl[2]);
                    mma16816(c[2*np],   qal, kbh[0], kbh[2]);
                    mma16816(c[2*np+1], qah, kbh[1], kbh[3]);
                    mma16816(c[2*np+1], qah, kbl[1], kbl[3]);
                    mma16816(c[2*np+1], qal, kbh[1], kbh[3]);
                }
            }

            bool needmask = (j0 + 63) > (i0 + wr0);
            float mxlo = -1e30f, mxhi = -1e30f;
#pragma unroll
            for (int nt = 0; nt < 8; nt++) {
                float s0 = c[nt][0] * SC, s1 = c[nt][1] * SC;
                float s2 = c[nt][2] * SC, s3 = c[nt][3] * SC;
                if (needmask) {
                    int j = j0 + nt * 8 + colb;
                    if (j     > gi_lo) s0 = -1e30f;
                    if (j + 1 > gi_lo) s1 = -1e30f;
                    if (j     > gi_hi) s2 = -1e30f;
                    if (j + 1 > gi_hi) s3 = -1e30f;
                }
                c[nt][0] = s0; c[nt][1] = s1; c[nt][2] = s2; c[nt][3] = s3;
                mxlo = fmaxf(mxlo, fmaxf(s0, s1));
                mxhi = fmaxf(mxhi, fmaxf(s2, s3));
            }
            mxlo = fmaxf(mxlo, __shfl_xor_sync(0xffffffffu, mxlo, 1));
            mxlo = fmaxf(mxlo, __shfl_xor_sync(0xffffffffu, mxlo, 2));
            mxhi = fmaxf(mxhi, __shfl_xor_sync(0xffffffffu, mxhi, 1));
            mxhi = fmaxf(mxhi, __shfl_xor_sync(0xffffffffu, mxhi, 2));
            float mnlo = fmaxf(m_lo, mxlo), mnhi = fmaxf(m_hi, mxhi);
            float alo = __expf(m_lo - mnlo), ahi = __expf(m_hi - mnhi);
            float slo = 0.0f, shi = 0.0f;
#pragma unroll
            for (int nt = 0; nt < 8; nt++) {
                float p0 = __expf(c[nt][0] - mnlo);
                float p1 = __expf(c[nt][1] - mnlo);
                float p2 = __expf(c[nt][2] - mnhi);
                float p3 = __expf(c[nt][3] - mnhi);
                c[nt][0] = p0; c[nt][1] = p1; c[nt][2] = p2; c[nt][3] = p3;
                slo += p0 + p1; shi += p2 + p3;
            }
            slo += __shfl_xor_sync(0xffffffffu, slo, 1);
            slo += __shfl_xor_sync(0xffffffffu, slo, 2);
            shi += __shfl_xor_sync(0xffffffffu, shi, 1);
            shi += __shfl_xor_sync(0xffffffffu, shi, 2);
            l_lo = l_lo * alo + slo; m_lo = mnlo;
            l_hi = l_hi * ahi + shi; m_hi = mnhi;
#pragma unroll
            for (int nt = 0; nt < 8; nt++) {
                O[nt][0] *= alo; O[nt][1] *= alo;
                O[nt][2] *= ahi; O[nt][3] *= ahi;
            }

            uint32_t pah[4][4], pal[4][4];
#pragma unroll
            for (int kc = 0; kc < 4; kc++) {
#pragma unroll
                for (int half = 0; half < 2; half++) {
                    int nt = 2 * kc + half;
                    float x0 = c[nt][0], x1 = c[nt][1];
                    float y0 = c[nt][2], y1 = c[nt][3];
                    __nv_bfloat16 hx0 = __float2bfloat16(x0), hx1 = __float2bfloat16(x1);
                    __nv_bfloat16 hy0 = __float2bfloat16(y0), hy1 = __float2bfloat16(y1);
                    pah[kc][half * 2 + 0] = packbf(__bfloat162float(hx0), __bfloat162float(hx1));
                    pah[kc][half * 2 + 1] = packbf(__bfloat162float(hy0), __bfloat162float(hy1));
                    pal[kc][half * 2 + 0] = packbf(x0 - __bfloat162float(hx0), x1 - __bfloat162float(hx1));
                    pal[kc][half * 2 + 1] = packbf(y0 - __bfloat162float(hy0), y1 - __bfloat162float(hy1));
                }
            }

#pragma unroll
            for (int kc = 0; kc < 4; kc++) {
                uint32_t voffe = (uint32_t)(SB2 + 2 * KSZ + (kc * 16 + (lane & 15)) * LDK
                                            + (lane >> 4) * 8);
#pragma unroll
                for (int np = 0; np < 4; np++) {
                    uint32_t va = sb + (voffe + np * 16) * 2;
                    uint32_t vbh[4], vbl[4];
                    ldsm4t(vbh, va);
                    ldsm4t(vbl, va + KSZ * 2);
                    mma16816(O[2*np],   pah[kc], vbh[0], vbh[1]);
                    mma16816(O[2*np],   pah[kc], vbl[0], vbl[1]);
                    mma16816(O[2*np],   pal[kc], vbh[0], vbh[1]);
                    mma16816(O[2*np+1], pah[kc], vbh[2], vbh[3]);
                    mma16816(O[2*np+1], pah[kc], vbl[2], vbl[3]);
                    mma16816(O[2*np+1], pal[kc], vbh[2], vbh[3]);
                }
            }
        }
        __syncthreads();
    }

    float ivlo = 1.0f / l_lo, ivhi = 1.0f / l_hi;
    size_t rlo = (size_t)(bidx * Sm + gi_lo) * Dm;
    size_t rhi = (size_t)(bidx * Sm + gi_hi) * Dm;
#pragma unroll
    for (int nt = 0; nt < 8; nt++) {
        int col = hidx * DHm + nt * 8 + colb;
        float o0 = O[nt][0] * ivlo, o1 = O[nt][1] * ivlo;
        float o2 = O[nt][2] * ivhi, o3 = O[nt][3] * ivhi;
        __nv_bfloat16 h0 = __float2bfloat16(o0), h1 = __float2bfloat16(o1);
        __nv_bfloat16 h2 = __float2bfloat16(o2), h3 = __float2bfloat16(o3);
        *(uint32_t*)&g_ch[rlo + col] = packbf(__bfloat162float(h0), __bfloat162float(h1));
        *(uint32_t*)&g_ch[rhi + col] = packbf(__bfloat162float(h2), __bfloat162float(h3));
        *(uint32_t*)&g_cl[rlo + col] = packbf(o0 - __bfloat162float(h0), o1 - __bfloat162float(h1));
        *(uint32_t*)&g_cl[rhi + col] = packbf(o2 - __bfloat162float(h2), o3 - __bfloat162float(h3));
    }
}

// ---------------- launch ----------------
extern "C" void kernel_launch(void* const* d_in, const int* in_sizes, int n_in,
                              void* d_out, int out_size)
{
    const float* x      = (const float*)d_in[0];
    const float* qkv_w  = (const float*)d_in[1];
    const float* qkv_b  = (const float*)d_in[2];
    const float* proj_w = (const float*)d_in[3];
    const float* proj_b = (const float*)d_in[4];
    float* out = (float*)d_out;

    float* p_qkv;
    cudaGetSymbolAddress((void**)&p_qkv, g_qkv);
    __nv_bfloat16 *p_xh, *p_xl, *p_wh, *p_wl, *p_ch, *p_cl, *p_ph, *p_pl;
    cudaGetSymbolAddress((void**)&p_xh, g_xh);
    cudaGetSymbolAddress((void**)&p_xl, g_xl);
    cudaGetSymbolAddress((void**)&p_wh, g_wh);
    cudaGetSymbolAddress((void**)&p_wl, g_wl);
    cudaGetSymbolAddress((void**)&p_ch, g_ch);
    cudaGetSymbolAddress((void**)&p_cl, g_cl);
    cudaGetSymbolAddress((void**)&p_ph, g_ph);
    cudaGetSymbolAddress((void**)&p_pl, g_pl);

    int smem_gemm = 2 * STAGE_E * sizeof(__nv_bfloat16);   // 147456
    cudaFuncSetAttribute(mma_gemm_kernel, cudaFuncAttributeMaxDynamicSharedMemorySize, smem_gemm);
    int smem_attn = (2 * QSZ + 2 * STG) * sizeof(__nv_bfloat16);   // 110592
    cudaFuncSetAttribute(attn_mma_kernel, cudaFuncAttributeMaxDynamicSharedMemorySize, smem_attn);

    // 1) split inputs (+ proj_w early; independent of everything else)
    split_kernel<<<(MROWS * Dm / 4 + 255) / 256, 256>>>(x, p_xh, p_xl, MROWS * Dm / 4);
    split_kernel<<<(QKVN * Dm / 4 + 255) / 256, 256>>>(qkv_w, p_wh, p_wl, QKVN * Dm / 4);
    split_kernel<<<(Dm * Dm / 4 + 255) / 256, 256>>>(proj_w, p_ph, p_pl, Dm * Dm / 4);
    rope_freq_kernel<<<1, 32>>>();
    rope_table_kernel<<<(Sm * DHm + 255) / 256, 256>>>();

    // 2) QKV GEMM
    mma_gemm_kernel<<<dim3(QKVN / 128, MROWS / 128), 256, smem_gemm>>>(
        p_xh, p_xl, p_wh, p_wl, qkv_b, p_qkv, MROWS, QKVN, Dm);

    // 3) fused rope/split
    rope_split_kernel<<<(Bm * Sm * Hm * DHm) / 256, 256>>>();

    // 4) flash attention (mma.sync, split bf16) -> g_ch/g_cl
    attn_mma_kernel<<<dim3(Sm / 128, Bm * Hm), 256, smem_attn>>>();

    // 5) proj GEMM
    mma_gemm_kernel<<<dim3(Dm / 128, MROWS / 128), 256, smem_gemm>>>(
        p_ch, p_cl, p_ph, p_pl, proj_b, out, MROWS, Dm, Dm);
}

// round 9
// speedup vs baseline: 3.0159x; 1.1109x over previous
#include <cuda_runtime.h>
#include <cuda_bf16.h>
#include <math.h>
#include <stdint.h>

#define Bm   2
#define Sm   2048
#define Dm   1024
#define Hm   16
#define DHm  64
#define MROWS (Bm*Sm)      // 4096
#define QKVN  (3*Dm)       // 3072

// ---------------- scratch (device globals; no allocation) ----------------
__device__ float g_qkv[MROWS * QKVN];     // [B*S, 3072] (q|k|v per head)
__device__ float g_cos[Sm * DHm];
__device__ float g_sin[Sm * DHm];

// bf16 split buffers
__device__ __nv_bfloat16 g_xh [MROWS * Dm];
__device__ __nv_bfloat16 g_xl [MROWS * Dm];
__device__ __nv_bfloat16 g_wh [QKVN * Dm];
__device__ __nv_bfloat16 g_wl [QKVN * Dm];
__device__ __nv_bfloat16 g_ph [Dm * Dm];
__device__ __nv_bfloat16 g_pl [Dm * Dm];
// rope'd q/k (hi only) and v (hi/lo), [B,H,S,Dh]
__device__ __nv_bfloat16 g_qh [Bm*Hm*Sm*DHm];
__device__ __nv_bfloat16 g_kh [Bm*Hm*Sm*DHm];
__device__ __nv_bfloat16 g_vh [Bm*Hm*Sm*DHm];
__device__ __nv_bfloat16 g_vl [Bm*Hm*Sm*DHm];
// attention context, bf16 hi/lo [B*S, D]
__device__ __nv_bfloat16 g_ch [MROWS * Dm];
__device__ __nv_bfloat16 g_cl [MROWS * Dm];

// ---------------- helpers ----------------
__device__ __forceinline__ uint32_t smem_u32(const void* p) {
    uint32_t a;
    asm("{ .reg .u64 t; cvta.to.shared.u64 t, %1; cvt.u32.u64 %0, t; }" : "=r"(a) : "l"(p));
    return a;
}
__device__ __forceinline__ void ldsm4(uint32_t* r, uint32_t addr) {
    asm volatile("ldmatrix.sync.aligned.m8n8.x4.shared.b16 {%0,%1,%2,%3}, [%4];"
                 : "=r"(r[0]), "=r"(r[1]), "=r"(r[2]), "=r"(r[3]) : "r"(addr));
}
__device__ __forceinline__ void ldsm4t(uint32_t* r, uint32_t addr) {
    asm volatile("ldmatrix.sync.aligned.m8n8.x4.trans.shared.b16 {%0,%1,%2,%3}, [%4];"
                 : "=r"(r[0]), "=r"(r[1]), "=r"(r[2]), "=r"(r[3]) : "r"(addr));
}
__device__ __forceinline__ void mma16816(float* c, const uint32_t* a, uint32_t b0, uint32_t b1) {
    asm volatile("mma.sync.aligned.m16n8k16.row.col.f32.bf16.bf16.f32 "
                 "{%0,%1,%2,%3}, {%4,%5,%6,%7}, {%8,%9}, {%0,%1,%2,%3};"
                 : "+f"(c[0]), "+f"(c[1]), "+f"(c[2]), "+f"(c[3])
                 : "r"(a[0]), "r"(a[1]), "r"(a[2]), "r"(a[3]), "r"(b0), "r"(b1));
}
__device__ __forceinline__ uint32_t packbf(float lo, float hi) {
    __nv_bfloat162 v = __floats2bfloat162_rn(lo, hi);
    return *(uint32_t*)&v;
}

// ---------------- combined split conversion (x, qkv_w, proj_w) ----------------
#define N1 (MROWS * Dm / 4)
#define N2 (QKVN * Dm / 4)
#define N3 (Dm * Dm / 4)

__global__ void split_all_kernel(const float* __restrict__ x,
                                 const float* __restrict__ qw,
                                 const float* __restrict__ pw) {
    int i = blockIdx.x * blockDim.x + threadIdx.x;
    const float* src;
    __nv_bfloat16 *hi, *lo;
    int off;
    if (i < N1)            { src = x;  hi = g_xh; lo = g_xl; off = i; }
    else if (i < N1 + N2)  { src = qw; hi = g_wh; lo = g_wl; off = i - N1; }
    else if (i < N1+N2+N3) { src = pw; hi = g_ph; lo = g_pl; off = i - N1 - N2; }
    else return;
    float4 v = ((const float4*)src)[off];
    __nv_bfloat16 h0 = __float2bfloat16(v.x), h1 = __float2bfloat16(v.y);
    __nv_bfloat16 h2 = __float2bfloat16(v.z), h3 = __float2bfloat16(v.w);
    __nv_bfloat16 l0 = __float2bfloat16(v.x - __bfloat162float(h0));
    __nv_bfloat16 l1 = __float2bfloat16(v.y - __bfloat162float(h1));
    __nv_bfloat16 l2 = __float2bfloat16(v.z - __bfloat162float(h2));
    __nv_bfloat16 l3 = __float2bfloat16(v.w - __bfloat162float(h3));
    ((__nv_bfloat162*)hi)[off * 2 + 0] = __nv_bfloat162(h0, h1);
    ((__nv_bfloat162*)hi)[off * 2 + 1] = __nv_bfloat162(h2, h3);
    ((__nv_bfloat162*)lo)[off * 2 + 0] = __nv_bfloat162(l0, l1);
    ((__nv_bfloat162*)lo)[off * 2 + 1] = __nv_bfloat162(l2, l3);
}

// ---------------- mma.sync split-bf16 GEMM, KC=64 double-buffered ----------------
#define KC 64
#define LDT 72
#define TILE_E (128*LDT)
#define STAGE_E (4*TILE_E)

__global__ __launch_bounds__(256)
void mma_gemm_kernel(const __nv_bfloat16* __restrict__ Ah, const __nv_bfloat16* __restrict__ Al,
                     const __nv_bfloat16* __restrict__ Bh, const __nv_bfloat16* __restrict__ Bl,
                     const float* __restrict__ bias, float* __restrict__ C,
                     int M, int N, int K)
{
    extern __shared__ __nv_bfloat16 sm[];
    int tid = threadIdx.x;
    int lane = tid & 31, wid = tid >> 5;
    int wm = wid & 1, wn = wid >> 1;
    int m0 = blockIdx.y * 128, n0 = blockIdx.x * 128;
    int NC = K / KC;
    uint32_t sb = smem_u32(sm);

    float acc[4][4][4];
#pragma unroll
    for (int mt = 0; mt < 4; mt++)
#pragma unroll
        for (int nt = 0; nt < 4; nt++)
#pragma unroll
            for (int r = 0; r < 4; r++) acc[mt][nt][r] = 0.0f;

    auto issue = [&](int kc, int stg) {
#pragma unroll
        for (int i = 0; i < 16; i++) {
            int c = tid + (i << 8);
            int tile = c >> 10;
            int r = (c >> 3) & 127;
            int q = c & 7;
            uint32_t sa = sb + (uint32_t)(stg * STAGE_E + tile * TILE_E + r * LDT + q * 8) * 2;
            const __nv_bfloat16* g;
            if (tile == 0)      g = Ah + (size_t)(m0 + r) * K;
            else if (tile == 1) g = Al + (size_t)(m0 + r) * K;
            else if (tile == 2) g = Bh + (size_t)(n0 + r) * K;
            else                g = Bl + (size_t)(n0 + r) * K;
            g += kc * KC + q * 8;
            asm volatile("cp.async.cg.shared.global [%0], [%1], 16;" :: "r"(sa), "l"(g));
        }
        asm volatile("cp.async.commit_group;" ::: "memory");
    };

    issue(0, 0);

    for (int kc = 0; kc < NC; kc++) {
        int stg = kc & 1;
        if (kc + 1 < NC) issue(kc + 1, (kc + 1) & 1);
        if (kc + 1 < NC)
            asm volatile("cp.async.wait_group 1;" ::: "memory");
        else
            asm volatile("cp.async.wait_group 0;" ::: "memory");
        __syncthreads();

        uint32_t abase = sb + (uint32_t)(stg * STAGE_E) * 2
                       + (uint32_t)((wm * 64 + (lane & 15)) * LDT + (lane >> 4) * 8) * 2;
        uint32_t bbase = sb + (uint32_t)(stg * STAGE_E + 2 * TILE_E) * 2
                       + (uint32_t)((wn * 32 + (lane & 15)) * LDT + (lane >> 4) * 8) * 2;

#pragma unroll
        for (int kt = 0; kt < 4; kt++) {
            uint32_t kb = (uint32_t)(kt * 16) * 2;
            uint32_t ah[4][4], al[4][4], bh[2][4], bl[2][4];
#pragma unroll
            for (int mt = 0; mt < 4; mt++) {
                uint32_t a = abase + (uint32_t)(mt * 16 * LDT) * 2 + kb;
                ldsm4(ah[mt], a);
                ldsm4(al[mt], a + (uint32_t)TILE_E * 2);
            }
#pragma unroll
            for (int nt2 = 0; nt2 < 2; nt2++) {
                uint32_t b = bbase + (uint32_t)(nt2 * 16 * LDT) * 2 + kb;
                ldsm4(bh[nt2], b);
                ldsm4(bl[nt2], b + (uint32_t)TILE_E * 2);
            }
#pragma unroll
            for (int mt = 0; mt < 4; mt++)
#pragma unroll
                for (int nt = 0; nt < 4; nt++) {
                    int n2 = nt >> 1, hf = nt & 1;
                    mma16816(acc[mt][nt], ah[mt], bh[n2][hf], bh[n2][hf + 2]);
                    mma16816(acc[mt][nt], ah[mt], bl[n2][hf], bl[n2][hf + 2]);
                    mma16816(acc[mt][nt], al[mt], bh[n2][hf], bh[n2][hf + 2]);
                }
        }
        __syncthreads();
    }

#pragma unroll
    for (int mt = 0; mt < 4; mt++) {
        int row = m0 + wm * 64 + mt * 16 + (lane >> 2);
#pragma unroll
        for (int nt = 0; nt < 4; nt++) {
            int col = n0 + wn * 32 + nt * 8 + (lane & 3) * 2;
            float b0 = bias[col], b1 = bias[col + 1];
            float2* p0 = (float2*)&C[(size_t)row * N + col];
            float2* p1 = (float2*)&C[(size_t)(row + 8) * N + col];
            *p0 = make_float2(acc[mt][nt][0] + b0, acc[mt][nt][1] + b1);
            *p1 = make_float2(acc[mt][nt][2] + b0, acc[mt][nt][3] + b1);
        }
    }
}

// ---------------- RoPE cos/sin table (inv_freq computed per-block in smem) ----------------
__global__ void rope_table_kernel() {
    __shared__ double sinv[32];
    int t = threadIdx.x;
    if (t < 32)
        sinv[t] = exp2(-(double)(2 * t) / 64.0 * 13.287712379549449);  // log2(10000)
    __syncthreads();
    int idx = blockIdx.x * blockDim.x + t;
    if (idx >= Sm * DHm) return;
    int s = idx >> 6, d = idx & 63, i = d & 31;
    double ang = fmod((double)s * sinv[i], 6.283185307179586476925287);
    float sn, cs;
    sincosf((float)ang, &sn, &cs);
    g_cos[idx] = cs;
    g_sin[idx] = sn;
}

// ---------------- fused RoPE + split -> bf16 q/k (hi), v (hi/lo) ----------------
__global__ void rope_split_kernel() {
    int idx = blockIdx.x * blockDim.x + threadIdx.x;
    int d = idx & 63;
    int h = (idx >> 6) & 15;
    int s = (idx >> 10) & 2047;
    int b = idx >> 21;
    int base = (b * Sm + s) * QKVN + h * DHm;
    float c  = g_cos[(s << 6) + d];
    float sn = g_sin[(s << 6) + d];
    int dp = d ^ 32;
    float sgn = (d < 32) ? -1.0f : 1.0f;
    float q  = g_qkv[base + d];
    float qp = g_qkv[base + dp];
    float k  = g_qkv[base + Dm + d];
    float kp = g_qkv[base + Dm + dp];
    float v  = g_qkv[base + 2 * Dm + d];
    float qr = fmaf(q, c, sgn * qp * sn);
    float kr = fmaf(k, c, sgn * kp * sn);
    int o = ((b * Hm + h) * Sm + s) * DHm + d;
    __nv_bfloat16 vh = __float2bfloat16(v);
    g_qh[o] = __float2bfloat16(qr);
    g_kh[o] = __float2bfloat16(kr);
    g_vh[o] = vh;
    g_vl[o] = __float2bfloat16(v - __bfloat162float(vh));
}

// ---------------- flash attention on mma.sync (causal) ----------------
// QK single-pass bf16 (error << budget); PV split 3-pass.
// 128 Q rows per CTA, 8 warps x 16 rows, 64-col K/V tiles, double-buffered cp.async.
#define LDK 72
#define QSZ (128*LDK)
#define KSZ (64*LDK)
#define STG (3*KSZ)              // kh, vh, vl

__global__ __launch_bounds__(256, 2)
void attn_mma_kernel() {
    extern __shared__ __nv_bfloat16 asm_[];
    uint32_t sb = smem_u32(asm_);
    int tid = threadIdx.x;
    int lane = tid & 31, w = tid >> 5;
    int bh = blockIdx.y;
    int bidx = bh >> 4, hidx = bh & 15;
    int i0 = blockIdx.x * 128;
    int wr0 = w * 16;
    int ntiles = 2 * blockIdx.x + 2;
    const float SC = 0.125f;

    // K/V tile jt -> stage stg: 1536 16B chunks, 6/thread
    auto issue_kv = [&](int jt, int stg) {
        int j0 = jt * 64;
#pragma unroll
        for (int i = 0; i < 6; i++) {
            int c = tid + (i << 8);
            int tile = c >> 9;               // 0=kh 1=vh 2=vl
            int r = (c >> 3) & 63;
            int q = c & 7;
            uint32_t sa = sb + (uint32_t)(QSZ + stg * STG + tile * KSZ + r * LDK + q * 8) * 2;
            const __nv_bfloat16* g;
            if (tile == 0)      g = g_kh;
            else if (tile == 1) g = g_vh;
            else                g = g_vl;
            g += ((size_t)bh * Sm + j0 + r) * DHm + q * 8;
            asm volatile("cp.async.cg.shared.global [%0], [%1], 16;" :: "r"(sa), "l"(g));
        }
        asm volatile("cp.async.commit_group;" ::: "memory");
    };

    // Q (hi only): 1024 chunks, 4/thread
#pragma unroll
    for (int i = 0; i < 4; i++) {
        int c = tid + (i << 8);
        int r = c >> 3, q = c & 7;
        uint32_t sa = sb + (uint32_t)(r * LDK + q * 8) * 2;
        const __nv_bfloat16* g = g_qh + ((size_t)bh * Sm + i0 + r) * DHm + q * 8;
        asm volatile("cp.async.cg.shared.global [%0], [%1], 16;" :: "r"(sa), "l"(g));
    }
    issue_kv(0, 0);
    asm volatile("cp.async.commit_group;" ::: "memory");

    float O[8][4];
#pragma unroll
    for (int nt = 0; nt < 8; nt++)
#pragma unroll
        for (int r = 0; r < 4; r++) O[nt][r] = 0.0f;
    float m_lo = -1e30f, m_hi = -1e30f, l_lo = 0.0f, l_hi = 0.0f;

    int gi_lo = i0 + wr0 + (lane >> 2);
    int gi_hi = gi_lo + 8;
    int colb = (lane & 3) << 1;

    for (int jt = 0; jt < ntiles; jt++) {
        int stg = jt & 1;
        int j0 = jt * 64;
        if (jt + 1 < ntiles) issue_kv(jt + 1, (jt + 1) & 1);
        if (jt + 1 < ntiles)
            asm volatile("cp.async.wait_group 1;" ::: "memory");
        else
            asm volatile("cp.async.wait_group 0;" ::: "memory");
        __syncthreads();

        bool skip = (j0 > i0 + wr0 + 15);
        if (!skip) {
            uint32_t SB2 = QSZ + stg * STG;
            // ---- S = Q K^T  (single-pass bf16) ----
            float c[8][4];
#pragma unroll
            for (int nt = 0; nt < 8; nt++)
#pragma unroll
                for (int r = 0; r < 4; r++) c[nt][r] = 0.0f;

            uint32_t qoffe = (uint32_t)((wr0 + (lane & 15)) * LDK + (lane >> 4) * 8);
            uint32_t koffe = (uint32_t)(((lane & 15)) * LDK + (lane >> 4) * 8);
#pragma unroll
            for (int kc = 0; kc < 4; kc++) {
                uint32_t qa = sb + (qoffe + kc * 16) * 2;
                uint32_t qah[4];
                ldsm4(qah, qa);
#pragma unroll
                for (int np = 0; np < 4; np++) {
                    uint32_t ka = sb + (SB2 + np * 16 * LDK + koffe + kc * 16) * 2;
                    uint32_t kbh[4];
                    ldsm4(kbh, ka);
                    mma16816(c[2*np],   qah, kbh[0], kbh[2]);
                    mma16816(c[2*np+1], qah, kbh[1], kbh[3]);
                }
            }

            // ---- softmax ----
            bool needmask = (j0 + 63) > (i0 + wr0);
            float mxlo = -1e30f, mxhi = -1e30f;
#pragma unroll
            for (int nt = 0; nt < 8; nt++) {
                float s0 = c[nt][0] * SC, s1 = c[nt][1] * SC;
                float s2 = c[nt][2] * SC, s3 = c[nt][3] * SC;
                if (needmask) {
                    int j = j0 + nt * 8 + colb;
                    if (j     > gi_lo) s0 = -1e30f;
                    if (j + 1 > gi_lo) s1 = -1e30f;
                    if (j     > gi_hi) s2 = -1e30f;
                    if (j + 1 > gi_hi) s3 = -1e30f;
                }
                c[nt][0] = s0; c[nt][1] = s1; c[nt][2] = s2; c[nt][3] = s3;
                mxlo = fmaxf(mxlo, fmaxf(s0, s1));
                mxhi = fmaxf(mxhi, fmaxf(s2, s3));
            }
            mxlo = fmaxf(mxlo, __shfl_xor_sync(0xffffffffu, mxlo, 1));
            mxlo = fmaxf(mxlo, __shfl_xor_sync(0xffffffffu, mxlo, 2));
            mxhi = fmaxf(mxhi, __shfl_xor_sync(0xffffffffu, mxhi, 1));
            mxhi = fmaxf(mxhi, __shfl_xor_sync(0xffffffffu, mxhi, 2));
            float mnlo = fmaxf(m_lo, mxlo), mnhi = fmaxf(m_hi, mxhi);
            float alo = __expf(m_lo - mnlo), ahi = __expf(m_hi - mnhi);
            float slo = 0.0f, shi = 0.0f;
#pragma unroll
            for (int nt = 0; nt < 8; nt++) {
                float p0 = __expf(c[nt][0] - mnlo);
                float p1 = __expf(c[nt][1] - mnlo);
                float p2 = __expf(c[nt][2] - mnhi);
                float p3 = __expf(c[nt][3] - mnhi);
                c[nt][0] = p0; c[nt][1] = p1; c[nt][2] = p2; c[nt][3] = p3;
                slo += p0 + p1; shi += p2 + p3;
            }
            slo += __shfl_xor_sync(0xffffffffu, slo, 1);
            slo += __shfl_xor_sync(0xffffffffu, slo, 2);
            shi += __shfl_xor_sync(0xffffffffu, shi, 1);
            shi += __shfl_xor_sync(0xffffffffu, shi, 2);
            l_lo = l_lo * alo + slo; m_lo = mnlo;
            l_hi = l_hi * ahi + shi; m_hi = mnhi;
#pragma unroll
            for (int nt = 0; nt < 8; nt++) {
                O[nt][0] *= alo; O[nt][1] *= alo;
                O[nt][2] *= ahi; O[nt][3] *= ahi;
            }

            // ---- pack P hi/lo into A-fragments ----
            uint32_t pah[4][4], pal[4][4];
#pragma unroll
            for (int kc = 0; kc < 4; kc++) {
#pragma unroll
                for (int half = 0; half < 2; half++) {
                    int nt = 2 * kc + half;
                    float x0 = c[nt][0], x1 = c[nt][1];
                    float y0 = c[nt][2], y1 = c[nt][3];
                    __nv_bfloat16 hx0 = __float2bfloat16(x0), hx1 = __float2bfloat16(x1);
                    __nv_bfloat16 hy0 = __float2bfloat16(y0), hy1 = __float2bfloat16(y1);
                    pah[kc][half * 2 + 0] = packbf(__bfloat162float(hx0), __bfloat162float(hx1));
                    pah[kc][half * 2 + 1] = packbf(__bfloat162float(hy0), __bfloat162float(hy1));
                    pal[kc][half * 2 + 0] = packbf(x0 - __bfloat162float(hx0), x1 - __bfloat162float(hx1));
                    pal[kc][half * 2 + 1] = packbf(y0 - __bfloat162float(hy0), y1 - __bfloat162float(hy1));
                }
            }

            // ---- O += P V  (3-pass split) ----
#pragma unroll
            for (int kc = 0; kc < 4; kc++) {
                uint32_t voffe = (uint32_t)(SB2 + KSZ + (kc * 16 + (lane & 15)) * LDK
                                            + (lane >> 4) * 8);
#pragma unroll
                for (int np = 0; np < 4; np++) {
                    uint32_t va = sb + (voffe + np * 16) * 2;
                    uint32_t vbh[4], vbl[4];
                    ldsm4t(vbh, va);
                    ldsm4t(vbl, va + KSZ * 2);
                    mma16816(O[2*np],   pah[kc], vbh[0], vbh[1]);
                    mma16816(O[2*np],   pah[kc], vbl[0], vbl[1]);
                    mma16816(O[2*np],   pal[kc], vbh[0], vbh[1]);
                    mma16816(O[2*np+1], pah[kc], vbh[2], vbh[3]);
                    mma16816(O[2*np+1], pah[kc], vbl[2], vbl[3]);
                    mma16816(O[2*np+1], pal[kc], vbh[2], vbh[3]);
                }
            }
        }
        __syncthreads();
    }

    float ivlo = 1.0f / l_lo, ivhi = 1.0f / l_hi;
    size_t rlo = (size_t)(bidx * Sm + gi_lo) * Dm;
    size_t rhi = (size_t)(bidx * Sm + gi_hi) * Dm;
#pragma unroll
    for (int nt = 0; nt < 8; nt++) {
        int col = hidx * DHm + nt * 8 + colb;
        float o0 = O[nt][0] * ivlo, o1 = O[nt][1] * ivlo;
        float o2 = O[nt][2] * ivhi, o3 = O[nt][3] * ivhi;
        __nv_bfloat16 h0 = __float2bfloat16(o0), h1 = __float2bfloat16(o1);
        __nv_bfloat16 h2 = __float2bfloat16(o2), h3 = __float2bfloat16(o3);
        *(uint32_t*)&g_ch[rlo + col] = packbf(__bfloat162float(h0), __bfloat162float(h1));
        *(uint32_t*)&g_ch[rhi + col] = packbf(__bfloat162float(h2), __bfloat162float(h3));
        *(uint32_t*)&g_cl[rlo + col] = packbf(o0 - __bfloat162float(h0), o1 - __bfloat162float(h1));
        *(uint32_t*)&g_cl[rhi + col] = packbf(o2 - __bfloat162float(h2), o3 - __bfloat162float(h3));
    }
}

// ---------------- launch ----------------
extern "C" void kernel_launch(void* const* d_in, const int* in_sizes, int n_in,
                              void* d_out, int out_size)
{
    const float* x      = (const float*)d_in[0];
    const float* qkv_w  = (const float*)d_in[1];
    const float* qkv_b  = (const float*)d_in[2];
    const float* proj_w = (const float*)d_in[3];
    const float* proj_b = (const float*)d_in[4];
    float* out = (float*)d_out;

    float* p_qkv;
    cudaGetSymbolAddress((void**)&p_qkv, g_qkv);
    __nv_bfloat16 *p_xh, *p_xl, *p_wh, *p_wl, *p_ch, *p_cl, *p_ph, *p_pl;
    cudaGetSymbolAddress((void**)&p_xh, g_xh);
    cudaGetSymbolAddress((void**)&p_xl, g_xl);
    cudaGetSymbolAddress((void**)&p_wh, g_wh);
    cudaGetSymbolAddress((void**)&p_wl, g_wl);
    cudaGetSymbolAddress((void**)&p_ch, g_ch);
    cudaGetSymbolAddress((void**)&p_cl, g_cl);
    cudaGetSymbolAddress((void**)&p_ph, g_ph);
    cudaGetSymbolAddress((void**)&p_pl, g_pl);

    int smem_gemm = 2 * STAGE_E * sizeof(__nv_bfloat16);   // 147456
    cudaFuncSetAttribute(mma_gemm_kernel, cudaFuncAttributeMaxDynamicSharedMemorySize, smem_gemm);
    int smem_attn = (QSZ + 2 * STG) * sizeof(__nv_bfloat16);   // 73728
    cudaFuncSetAttribute(attn_mma_kernel, cudaFuncAttributeMaxDynamicSharedMemorySize, smem_attn);

    // 1) split all inputs (one kernel) + rope table
    split_all_kernel<<<(N1 + N2 + N3 + 255) / 256, 256>>>(x, qkv_w, proj_w);
    rope_table_kernel<<<(Sm * DHm + 255) / 256, 256>>>();

    // 2) QKV GEMM
    mma_gemm_kernel<<<dim3(QKVN / 128, MROWS / 128), 256, smem_gemm>>>(
        p_xh, p_xl, p_wh, p_wl, qkv_b, p_qkv, MROWS, QKVN, Dm);

    // 3) fused rope/split
    rope_split_kernel<<<(Bm * Sm * Hm * DHm) / 256, 256>>>();

    // 4) flash attention -> g_ch/g_cl
    attn_mma_kernel<<<dim3(Sm / 128, Bm * Hm), 256, smem_attn>>>();

    // 5) proj GEMM
    mma_gemm_kernel<<<dim3(Dm / 128, MROWS / 128), 256, smem_gemm>>>(
        p_ch, p_cl, p_ph, p_pl, proj_b, out, MROWS, Dm, Dm);
}

// round 11
// speedup vs baseline: 3.3665x; 1.1163x over previous
#include <cuda_runtime.h>
#include <cuda_bf16.h>
#include <cuda_fp16.h>
#include <math.h>
#include <stdint.h>

#define Bm   2
#define Sm   2048
#define Dm   1024
#define Hm   16
#define DHm  64
#define MROWS (Bm*Sm)      // 4096
#define QKVN  (3*Dm)       // 3072

// ---------------- scratch (device globals; no allocation) ----------------
__device__ float g_qkv[MROWS * QKVN];     // [B*S, 3072] (q|k|v per head)
__device__ float g_cos[Sm * DHm];
__device__ float g_sin[Sm * DHm];

// bf16 split buffers (GEMM path)
__device__ __nv_bfloat16 g_xh [MROWS * Dm];
__device__ __nv_bfloat16 g_xl [MROWS * Dm];
__device__ __nv_bfloat16 g_wh [QKVN * Dm];
__device__ __nv_bfloat16 g_wl [QKVN * Dm];
__device__ __nv_bfloat16 g_ph [Dm * Dm];
__device__ __nv_bfloat16 g_pl [Dm * Dm];
// rope'd q/k/v, fp16, [B,H,S,Dh]
__device__ __half g_qf [Bm*Hm*Sm*DHm];
__device__ __half g_kf [Bm*Hm*Sm*DHm];
__device__ __half g_vf [Bm*Hm*Sm*DHm];
// attention context, bf16 hi/lo [B*S, D]
__device__ __nv_bfloat16 g_ch [MROWS * Dm];
__device__ __nv_bfloat16 g_cl [MROWS * Dm];

// ---------------- helpers ----------------
__device__ __forceinline__ uint32_t smem_u32(const void* p) {
    uint32_t a;
    asm("{ .reg .u64 t; cvta.to.shared.u64 t, %1; cvt.u32.u64 %0, t; }" : "=r"(a) : "l"(p));
    return a;
}
__device__ __forceinline__ void ldsm4(uint32_t* r, uint32_t addr) {
    asm volatile("ldmatrix.sync.aligned.m8n8.x4.shared.b16 {%0,%1,%2,%3}, [%4];"
                 : "=r"(r[0]), "=r"(r[1]), "=r"(r[2]), "=r"(r[3]) : "r"(addr));
}
__device__ __forceinline__ void ldsm4t(uint32_t* r, uint32_t addr) {
    asm volatile("ldmatrix.sync.aligned.m8n8.x4.trans.shared.b16 {%0,%1,%2,%3}, [%4];"
                 : "=r"(r[0]), "=r"(r[1]), "=r"(r[2]), "=r"(r[3]) : "r"(addr));
}
__device__ __forceinline__ void mma16816(float* c, const uint32_t* a, uint32_t b0, uint32_t b1) {
    asm volatile("mma.sync.aligned.m16n8k16.row.col.f32.bf16.bf16.f32 "
                 "{%0,%1,%2,%3}, {%4,%5,%6,%7}, {%8,%9}, {%0,%1,%2,%3};"
                 : "+f"(c[0]), "+f"(c[1]), "+f"(c[2]), "+f"(c[3])
                 : "r"(a[0]), "r"(a[1]), "r"(a[2]), "r"(a[3]), "r"(b0), "r"(b1));
}
__device__ __forceinline__ void mma16816h(float* c, const uint32_t* a, uint32_t b0, uint32_t b1) {
    asm volatile("mma.sync.aligned.m16n8k16.row.col.f32.f16.f16.f32 "
                 "{%0,%1,%2,%3}, {%4,%5,%6,%7}, {%8,%9}, {%0,%1,%2,%3};"
                 : "+f"(c[0]), "+f"(c[1]), "+f"(c[2]), "+f"(c[3])
                 : "r"(a[0]), "r"(a[1]), "r"(a[2]), "r"(a[3]), "r"(b0), "r"(b1));
}
__device__ __forceinline__ uint32_t packbf(float lo, float hi) {
    __nv_bfloat162 v = __floats2bfloat162_rn(lo, hi);
    return *(uint32_t*)&v;
}
__device__ __forceinline__ uint32_t packhf(float lo, float hi) {
    __half2 v = __floats2half2_rn(lo, hi);
    return *(uint32_t*)&v;
}

// ---------------- combined split conversion (x, qkv_w, proj_w) ----------------
#define N1 (MROWS * Dm / 4)
#define N2 (QKVN * Dm / 4)
#define N3 (Dm * Dm / 4)

__global__ void split_all_kernel(const float* __restrict__ x,
                                 const float* __restrict__ qw,
                                 const float* __restrict__ pw) {
    int i = blockIdx.x * blockDim.x + threadIdx.x;
    const float* src;
    __nv_bfloat16 *hi, *lo;
    int off;
    if (i < N1)            { src = x;  hi = g_xh; lo = g_xl; off = i; }
    else if (i < N1 + N2)  { src = qw; hi = g_wh; lo = g_wl; off = i - N1; }
    else if (i < N1+N2+N3) { src = pw; hi = g_ph; lo = g_pl; off = i - N1 - N2; }
    else return;
    float4 v = ((const float4*)src)[off];
    __nv_bfloat16 h0 = __float2bfloat16(v.x), h1 = __float2bfloat16(v.y);
    __nv_bfloat16 h2 = __float2bfloat16(v.z), h3 = __float2bfloat16(v.w);
    __nv_bfloat16 l0 = __float2bfloat16(v.x - __bfloat162float(h0));
    __nv_bfloat16 l1 = __float2bfloat16(v.y - __bfloat162float(h1));
    __nv_bfloat16 l2 = __float2bfloat16(v.z - __bfloat162float(h2));
    __nv_bfloat16 l3 = __float2bfloat16(v.w - __bfloat162float(h3));
    ((__nv_bfloat162*)hi)[off * 2 + 0] = __nv_bfloat162(h0, h1);
    ((__nv_bfloat162*)hi)[off * 2 + 1] = __nv_bfloat162(h2, h3);
    ((__nv_bfloat162*)lo)[off * 2 + 0] = __nv_bfloat162(l0, l1);
    ((__nv_bfloat162*)lo)[off * 2 + 1] = __nv_bfloat162(l2, l3);
}

// ---------------- mma.sync split-bf16 GEMM, KC=64 double-buffered ----------------
#define KC 64
#define LDT 72
#define TILE_E (128*LDT)
#define STAGE_E (4*TILE_E)

__global__ __launch_bounds__(256)
void mma_gemm_kernel(const __nv_bfloat16* __restrict__ Ah, const __nv_bfloat16* __restrict__ Al,
                     const __nv_bfloat16* __restrict__ Bh, const __nv_bfloat16* __restrict__ Bl,
                     const float* __restrict__ bias, float* __restrict__ C,
                     int M, int N, int K)
{
    extern __shared__ __nv_bfloat16 sm[];
    int tid = threadIdx.x;
    int lane = tid & 31, wid = tid >> 5;
    int wm = wid & 1, wn = wid >> 1;
    int m0 = blockIdx.y * 128, n0 = blockIdx.x * 128;
    int NC = K / KC;
    uint32_t sb = smem_u32(sm);

    float acc[4][4][4];
#pragma unroll
    for (int mt = 0; mt < 4; mt++)
#pragma unroll
        for (int nt = 0; nt < 4; nt++)
#pragma unroll
            for (int r = 0; r < 4; r++) acc[mt][nt][r] = 0.0f;

    auto issue = [&](int kc, int stg) {
#pragma unroll
        for (int i = 0; i < 16; i++) {
            int c = tid + (i << 8);
            int tile = c >> 10;
            int r = (c >> 3) & 127;
            int q = c & 7;
            uint32_t sa = sb + (uint32_t)(stg * STAGE_E + tile * TILE_E + r * LDT + q * 8) * 2;
            const __nv_bfloat16* g;
            if (tile == 0)      g = Ah + (size_t)(m0 + r) * K;
            else if (tile == 1) g = Al + (size_t)(m0 + r) * K;
            else if (tile == 2) g = Bh + (size_t)(n0 + r) * K;
            else                g = Bl + (size_t)(n0 + r) * K;
            g += kc * KC + q * 8;
            asm volatile("cp.async.cg.shared.global [%0], [%1], 16;" :: "r"(sa), "l"(g));
        }
        asm volatile("cp.async.commit_group;" ::: "memory");
    };

    issue(0, 0);

    for (int kc = 0; kc < NC; kc++) {
        int stg = kc & 1;
        if (kc + 1 < NC) issue(kc + 1, (kc + 1) & 1);
        if (kc + 1 < NC)
            asm volatile("cp.async.wait_group 1;" ::: "memory");
        else
            asm volatile("cp.async.wait_group 0;" ::: "memory");
        __syncthreads();

        uint32_t abase = sb + (uint32_t)(stg * STAGE_E) * 2
                       + (uint32_t)((wm * 64 + (lane & 15)) * LDT + (lane >> 4) * 8) * 2;
        uint32_t bbase = sb + (uint32_t)(stg * STAGE_E + 2 * TILE_E) * 2
                       + (uint32_t)((wn * 32 + (lane & 15)) * LDT + (lane >> 4) * 8) * 2;

#pragma unroll
        for (int kt = 0; kt < 4; kt++) {
            uint32_t kb = (uint32_t)(kt * 16) * 2;
            uint32_t ah[4][4], al[4][4], bh[2][4], bl[2][4];
#pragma unroll
            for (int mt = 0; mt < 4; mt++) {
                uint32_t a = abase + (uint32_t)(mt * 16 * LDT) * 2 + kb;
                ldsm4(ah[mt], a);
                ldsm4(al[mt], a + (uint32_t)TILE_E * 2);
            }
#pragma unroll
            for (int nt2 = 0; nt2 < 2; nt2++) {
                uint32_t b = bbase + (uint32_t)(nt2 * 16 * LDT) * 2 + kb;
                ldsm4(bh[nt2], b);
                ldsm4(bl[nt2], b + (uint32_t)TILE_E * 2);
            }
#pragma unroll
            for (int mt = 0; mt < 4; mt++)
#pragma unroll
                for (int nt = 0; nt < 4; nt++) {
                    int n2 = nt >> 1, hf = nt & 1;
                    mma16816(acc[mt][nt], ah[mt], bh[n2][hf], bh[n2][hf + 2]);
                    mma16816(acc[mt][nt], ah[mt], bl[n2][hf], bl[n2][hf + 2]);
                    mma16816(acc[mt][nt], al[mt], bh[n2][hf], bh[n2][hf + 2]);
                }
        }
        __syncthreads();
    }

#pragma unroll
    for (int mt = 0; mt < 4; mt++) {
        int row = m0 + wm * 64 + mt * 16 + (lane >> 2);
#pragma unroll
        for (int nt = 0; nt < 4; nt++) {
            int col = n0 + wn * 32 + nt * 8 + (lane & 3) * 2;
            float b0 = bias[col], b1 = bias[col + 1];
            float2* p0 = (float2*)&C[(size_t)row * N + col];
            float2* p1 = (float2*)&C[(size_t)(row + 8) * N + col];
            *p0 = make_float2(acc[mt][nt][0] + b0, acc[mt][nt][1] + b1);
            *p1 = make_float2(acc[mt][nt][2] + b0, acc[mt][nt][3] + b1);
        }
    }
}

// ---------------- RoPE cos/sin table ----------------
__global__ void rope_table_kernel() {
    __shared__ double sinv[32];
    int t = threadIdx.x;
    if (t < 32)
        sinv[t] = exp2(-(double)(2 * t) / 64.0 * 13.287712379549449);  // log2(10000)
    __syncthreads();
    int idx = blockIdx.x * blockDim.x + t;
    if (idx >= Sm * DHm) return;
    int s = idx >> 6, d = idx & 63, i = d & 31;
    double ang = fmod((double)s * sinv[i], 6.283185307179586476925287);
    float sn, cs;
    sincosf((float)ang, &sn, &cs);
    g_cos[idx] = cs;
    g_sin[idx] = sn;
}

// ---------------- fused RoPE + convert -> fp16 q/k/v in [B,H,S,Dh] ----------------
__global__ void rope_split_kernel() {
    int idx = blockIdx.x * blockDim.x + threadIdx.x;
    int d = idx & 63;
    int h = (idx >> 6) & 15;
    int s = (idx >> 10) & 2047;
    int b = idx >> 21;
    int base = (b * Sm + s) * QKVN + h * DHm;
    float c  = g_cos[(s << 6) + d];
    float sn = g_sin[(s << 6) + d];
    int dp = d ^ 32;
    float sgn = (d < 32) ? -1.0f : 1.0f;
    float q  = g_qkv[base + d];
    float qp = g_qkv[base + dp];
    float k  = g_qkv[base + Dm + d];
    float kp = g_qkv[base + Dm + dp];
    float v  = g_qkv[base + 2 * Dm + d];
    float qr = fmaf(q, c, sgn * qp * sn);
    float kr = fmaf(k, c, sgn * kp * sn);
    int o = ((b * Hm + h) * Sm + s) * DHm + d;
    g_qf[o] = __float2half(qr);
    g_kf[o] = __float2half(kr);
    g_vf[o] = __float2half(v);
}

// ---------------- flash attention on mma.sync fp16 (causal) ----------------
// QK and PV both single-pass fp16 (error model: ~1e-4 final L2 rel err).
// 128 Q rows per CTA, 8 warps x 16 rows, 64-col K/V tiles, double-buffered cp.async.
#define LDK 72
#define QSZ (128*LDK)
#define KSZ (64*LDK)
#define STG (2*KSZ)              // kf, vf

__global__ __launch_bounds__(256, 2)
void attn_mma_kernel() {
    extern __shared__ __half asm_[];
    uint32_t sb = smem_u32(asm_);
    int tid = threadIdx.x;
    int lane = tid & 31, w = tid >> 5;
    int bh = blockIdx.y;
    int bidx = bh >> 4, hidx = bh & 15;
    int i0 = blockIdx.x * 128;
    int wr0 = w * 16;
    int ntiles = 2 * blockIdx.x + 2;
    const float SC = 0.125f;

    // K/V tile jt -> stage stg: 1024 16B chunks, 4/thread
    auto issue_kv = [&](int jt, int stg) {
        int j0 = jt * 64;
#pragma unroll
        for (int i = 0; i < 4; i++) {
            int c = tid + (i << 8);
            int tile = c >> 9;               // 0=kf 1=vf
            int r = (c >> 3) & 63;
            int q = c & 7;
            uint32_t sa = sb + (uint32_t)(QSZ + stg * STG + tile * KSZ + r * LDK + q * 8) * 2;
            const __half* g = (tile == 0) ? g_kf : g_vf;
            g += ((size_t)bh * Sm + j0 + r) * DHm + q * 8;
            asm volatile("cp.async.cg.shared.global [%0], [%1], 16;" :: "r"(sa), "l"(g));
        }
        asm volatile("cp.async.commit_group;" ::: "memory");
    };

    // Q: 1024 chunks, 4/thread
#pragma unroll
    for (int i = 0; i < 4; i++) {
        int c = tid + (i << 8);
        int r = c >> 3, q = c & 7;
        uint32_t sa = sb + (uint32_t)(r * LDK + q * 8) * 2;
        const __half* g = g_qf + ((size_t)bh * Sm + i0 + r) * DHm + q * 8;
        asm volatile("cp.async.cg.shared.global [%0], [%1], 16;" :: "r"(sa), "l"(g));
    }
    issue_kv(0, 0);
    asm volatile("cp.async.commit_group;" ::: "memory");

    float O[8][4];
#pragma unroll
    for (int nt = 0; nt < 8; nt++)
#pragma unroll
        for (int r = 0; r < 4; r++) O[nt][r] = 0.0f;
    float m_lo = -1e30f, m_hi = -1e30f, l_lo = 0.0f, l_hi = 0.0f;

    int gi_lo = i0 + wr0 + (lane >> 2);
    int gi_hi = gi_lo + 8;
    int colb = (lane & 3) << 1;

    for (int jt = 0; jt < ntiles; jt++) {
        int stg = jt & 1;
        int j0 = jt * 64;
        if (jt + 1 < ntiles) issue_kv(jt + 1, (jt + 1) & 1);
        if (jt + 1 < ntiles)
            asm volatile("cp.async.wait_group 1;" ::: "memory");
        else
            asm volatile("cp.async.wait_group 0;" ::: "memory");
        __syncthreads();

        bool skip = (j0 > i0 + wr0 + 15);
        if (!skip) {
            uint32_t SB2 = QSZ + stg * STG;
            // ---- S = Q K^T  (single-pass fp16) ----
            float c[8][4];
#pragma unroll
            for (int nt = 0; nt < 8; nt++)
#pragma unroll
                for (int r = 0; r < 4; r++) c[nt][r] = 0.0f;

            uint32_t qoffe = (uint32_t)((wr0 + (lane & 15)) * LDK + (lane >> 4) * 8);
            uint32_t koffe = (uint32_t)(((lane & 15)) * LDK + (lane >> 4) * 8);
#pragma unroll
            for (int kc = 0; kc < 4; kc++) {
                uint32_t qa = sb + (qoffe + kc * 16) * 2;
                uint32_t qah[4];
                ldsm4(qah, qa);
#pragma unroll
                for (int np = 0; np < 4; np++) {
                    uint32_t ka = sb + (SB2 + np * 16 * LDK + koffe + kc * 16) * 2;
                    uint32_t kbh[4];
                    ldsm4(kbh, ka);
                    mma16816h(c[2*np],   qah, kbh[0], kbh[2]);
                    mma16816h(c[2*np+1], qah, kbh[1], kbh[3]);
                }
            }

            // ---- softmax ----
            bool needmask = (j0 + 63) > (i0 + wr0);
            float mxlo = -1e30f, mxhi = -1e30f;
#pragma unroll
            for (int nt = 0; nt < 8; nt++) {
                float s0 = c[nt][0] * SC, s1 = c[nt][1] * SC;
                float s2 = c[nt][2] * SC, s3 = c[nt][3] * SC;
                if (needmask) {
                    int j = j0 + nt * 8 + colb;
                    if (j     > gi_lo) s0 = -1e30f;
                    if (j + 1 > gi_lo) s1 = -1e30f;
                    if (j     > gi_hi) s2 = -1e30f;
                    if (j + 1 > gi_hi) s3 = -1e30f;
                }
                c[nt][0] = s0; c[nt][1] = s1; c[nt][2] = s2; c[nt][3] = s3;
                mxlo = fmaxf(mxlo, fmaxf(s0, s1));
                mxhi = fmaxf(mxhi, fmaxf(s2, s3));
            }
            mxlo = fmaxf(mxlo, __shfl_xor_sync(0xffffffffu, mxlo, 1));
            mxlo = fmaxf(mxlo, __shfl_xor_sync(0xffffffffu, mxlo, 2));
            mxhi = fmaxf(mxhi, __shfl_xor_sync(0xffffffffu, mxhi, 1));
            mxhi = fmaxf(mxhi, __shfl_xor_sync(0xffffffffu, mxhi, 2));
            float mnlo = fmaxf(m_lo, mxlo), mnhi = fmaxf(m_hi, mxhi);
            float alo = __expf(m_lo - mnlo), ahi = __expf(m_hi - mnhi);
            float slo = 0.0f, shi = 0.0f;
#pragma unroll
            for (int nt = 0; nt < 8; nt++) {
                float p0 = __expf(c[nt][0] - mnlo);
                float p1 = __expf(c[nt][1] - mnlo);
                float p2 = __expf(c[nt][2] - mnhi);
                float p3 = __expf(c[nt][3] - mnhi);
                c[nt][0] = p0; c[nt][1] = p1; c[nt][2] = p2; c[nt][3] = p3;
                slo += p0 + p1; shi += p2 + p3;
            }
            slo += __shfl_xor_sync(0xffffffffu, slo, 1);
            slo += __shfl_xor_sync(0xffffffffu, slo, 2);
            shi += __shfl_xor_sync(0xffffffffu, shi, 1);
            shi += __shfl_xor_sync(0xffffffffu, shi, 2);
            l_lo = l_lo * alo + slo; m_lo = mnlo;
            l_hi = l_hi * ahi + shi; m_hi = mnhi;
#pragma unroll
            for (int nt = 0; nt < 8; nt++) {
                O[nt][0] *= alo; O[nt][1] *= alo;
                O[nt][2] *= ahi; O[nt][3] *= ahi;
            }

            // ---- pack P into fp16 A-fragments (single precision pass) ----
            uint32_t pah[4][4];
#pragma unroll
            for (int kc = 0; kc < 4; kc++) {
#pragma unroll
                for (int half = 0; half < 2; half++) {
                    int nt = 2 * kc + half;
                    pah[kc][half * 2 + 0] = packhf(c[nt][0], c[nt][1]);
                    pah[kc][half * 2 + 1] = packhf(c[nt][2], c[nt][3]);
                }
            }

            // ---- O += P V  (single-pass fp16) ----
#pragma unroll
            for (int kc = 0; kc < 4; kc++) {
                uint32_t voffe = (uint32_t)(SB2 + KSZ + (kc * 16 + (lane & 15)) * LDK
                                            + (lane >> 4) * 8);
#pragma unroll
                for (int np = 0; np < 4; np++) {
                    uint32_t va = sb + (voffe + np * 16) * 2;
                    uint32_t vbh[4];
                    ldsm4t(vbh, va);
                    mma16816h(O[2*np],   pah[kc], vbh[0], vbh[1]);
                    mma16816h(O[2*np+1], pah[kc], vbh[2], vbh[3]);
                }
            }
        }
        __syncthreads();
    }

    float ivlo = 1.0f / l_lo, ivhi = 1.0f / l_hi;
    size_t rlo = (size_t)(bidx * Sm + gi_lo) * Dm;
    size_t rhi = (size_t)(bidx * Sm + gi_hi) * Dm;
#pragma unroll
    for (int nt = 0; nt < 8; nt++) {
        int col = hidx * DHm + nt * 8 + colb;
        float o0 = O[nt][0] * ivlo, o1 = O[nt][1] * ivlo;
        float o2 = O[nt][2] * ivhi, o3 = O[nt][3] * ivhi;
        __nv_bfloat16 h0 = __float2bfloat16(o0), h1 = __float2bfloat16(o1);
        __nv_bfloat16 h2 = __float2bfloat16(o2), h3 = __float2bfloat16(o3);
        *(uint32_t*)&g_ch[rlo + col] = packbf(__bfloat162float(h0), __bfloat162float(h1));
        *(uint32_t*)&g_ch[rhi + col] = packbf(__bfloat162float(h2), __bfloat162float(h3));
        *(uint32_t*)&g_cl[rlo + col] = packbf(o0 - __bfloat162float(h0), o1 - __bfloat162float(h1));
        *(uint32_t*)&g_cl[rhi + col] = packbf(o2 - __bfloat162float(h2), o3 - __bfloat162float(h3));
    }
}

// ---------------- launch ----------------
extern "C" void kernel_launch(void* const* d_in, const int* in_sizes, int n_in,
                              void* d_out, int out_size)
{
    const float* x      = (const float*)d_in[0];
    const float* qkv_w  = (const float*)d_in[1];
    const float* qkv_b  = (const float*)d_in[2];
    const float* proj_w = (const float*)d_in[3];
    const float* proj_b = (const float*)d_in[4];
    float* out = (float*)d_out;

    float* p_qkv;
    cudaGetSymbolAddress((void**)&p_qkv, g_qkv);
    __nv_bfloat16 *p_xh, *p_xl, *p_wh, *p_wl, *p_ch, *p_cl, *p_ph, *p_pl;
    cudaGetSymbolAddress((void**)&p_xh, g_xh);
    cudaGetSymbolAddress((void**)&p_xl, g_xl);
    cudaGetSymbolAddress((void**)&p_wh, g_wh);
    cudaGetSymbolAddress((void**)&p_wl, g_wl);
    cudaGetSymbolAddress((void**)&p_ch, g_ch);
    cudaGetSymbolAddress((void**)&p_cl, g_cl);
    cudaGetSymbolAddress((void**)&p_ph, g_ph);
    cudaGetSymbolAddress((void**)&p_pl, g_pl);

    int smem_gemm = 2 * STAGE_E * sizeof(__nv_bfloat16);   // 147456
    cudaFuncSetAttribute(mma_gemm_kernel, cudaFuncAttributeMaxDynamicSharedMemorySize, smem_gemm);
    int smem_attn = (QSZ + 2 * STG) * sizeof(__half);      // 55296
    cudaFuncSetAttribute(attn_mma_kernel, cudaFuncAttributeMaxDynamicSharedMemorySize, smem_attn);

    // 1) split all inputs (one kernel) + rope table
    split_all_kernel<<<(N1 + N2 + N3 + 255) / 256, 256>>>(x, qkv_w, proj_w);
    rope_table_kernel<<<(Sm * DHm + 255) / 256, 256>>>();

    // 2) QKV GEMM
    mma_gemm_kernel<<<dim3(QKVN / 128, MROWS / 128), 256, smem_gemm>>>(
        p_xh, p_xl, p_wh, p_wl, qkv_b, p_qkv, MROWS, QKVN, Dm);

    // 3) fused rope/convert
    rope_split_kernel<<<(Bm * Sm * Hm * DHm) / 256, 256>>>();

    // 4) flash attention (fp16 mma) -> g_ch/g_cl
    attn_mma_kernel<<<dim3(Sm / 128, Bm * Hm), 256, smem_attn>>>();

    // 5) proj GEMM
    mma_gemm_kernel<<<dim3(Dm / 128, MROWS / 128), 256, smem_gemm>>>(
        p_ch, p_cl, p_ph, p_pl, proj_b, out, MROWS, Dm, Dm);
}

// round 12
// speedup vs baseline: 6.6271x; 1.9685x over previous
#include <cuda_runtime.h>
#include <cuda_bf16.h>
#include <cuda_fp16.h>
#include <math.h>
#include <stdint.h>

#define Bm   2
#define Sm   2048
#define Dm   1024
#define Hm   16
#define DHm  64
#define MROWS (Bm*Sm)      // 4096
#define QKVN  (3*Dm)       // 3072

// ---------------- scratch (device globals; no allocation) ----------------
__device__ float g_cos[Sm * DHm];
__device__ float g_sin[Sm * DHm];

// fp16 buffers
__device__ __half g_xf [MROWS * Dm];      // x
__device__ __half g_wf [QKVN * Dm];       // qkv_w
__device__ __half g_pf [Dm * Dm];         // proj_w
__device__ __half g_qkvh[MROWS * QKVN];   // qkv output (fp16)
// rope'd q/k/v, fp16, [B,H,S,Dh]
__device__ __half g_qf [Bm*Hm*Sm*DHm];
__device__ __half g_kf [Bm*Hm*Sm*DHm];
__device__ __half g_vf [Bm*Hm*Sm*DHm];
// attention context, fp16 [B*S, D]
__device__ __half g_cf [MROWS * Dm];

// ---------------- helpers ----------------
__device__ __forceinline__ uint32_t smem_u32(const void* p) {
    uint32_t a;
    asm("{ .reg .u64 t; cvta.to.shared.u64 t, %1; cvt.u32.u64 %0, t; }" : "=r"(a) : "l"(p));
    return a;
}
__device__ __forceinline__ void ldsm4(uint32_t* r, uint32_t addr) {
    asm volatile("ldmatrix.sync.aligned.m8n8.x4.shared.b16 {%0,%1,%2,%3}, [%4];"
                 : "=r"(r[0]), "=r"(r[1]), "=r"(r[2]), "=r"(r[3]) : "r"(addr));
}
__device__ __forceinline__ void ldsm4t(uint32_t* r, uint32_t addr) {
    asm volatile("ldmatrix.sync.aligned.m8n8.x4.trans.shared.b16 {%0,%1,%2,%3}, [%4];"
                 : "=r"(r[0]), "=r"(r[1]), "=r"(r[2]), "=r"(r[3]) : "r"(addr));
}
__device__ __forceinline__ void mma16816h(float* c, const uint32_t* a, uint32_t b0, uint32_t b1) {
    asm volatile("mma.sync.aligned.m16n8k16.row.col.f32.f16.f16.f32 "
                 "{%0,%1,%2,%3}, {%4,%5,%6,%7}, {%8,%9}, {%0,%1,%2,%3};"
                 : "+f"(c[0]), "+f"(c[1]), "+f"(c[2]), "+f"(c[3])
                 : "r"(a[0]), "r"(a[1]), "r"(a[2]), "r"(a[3]), "r"(b0), "r"(b1));
}
__device__ __forceinline__ uint32_t packhf(float lo, float hi) {
    __half2 v = __floats2half2_rn(lo, hi);
    return *(uint32_t*)&v;
}

// ---------------- combined fp32->fp16 convert (x, qkv_w, proj_w) ----------------
#define N1 (MROWS * Dm / 4)
#define N2 (QKVN * Dm / 4)
#define N3 (Dm * Dm / 4)

__global__ void conv_all_kernel(const float* __restrict__ x,
                                const float* __restrict__ qw,
                                const float* __restrict__ pw) {
    int i = blockIdx.x * blockDim.x + threadIdx.x;
    const float* src;
    __half* dst;
    int off;
    if (i < N1)            { src = x;  dst = g_xf; off = i; }
    else if (i < N1 + N2)  { src = qw; dst = g_wf; off = i - N1; }
    else if (i < N1+N2+N3) { src = pw; dst = g_pf; off = i - N1 - N2; }
    else return;
    float4 v = ((const float4*)src)[off];
    ((__half2*)dst)[off * 2 + 0] = __floats2half2_rn(v.x, v.y);
    ((__half2*)dst)[off * 2 + 1] = __floats2half2_rn(v.z, v.w);
}

// ---------------- mma.sync single-pass fp16 GEMM, KC=64 double-buffered ----------------
// C[m,n] = sum_k A[m,k]*B[n,k] + bias[n]
#define KC 64
#define LDT 72
#define TILE_E (128*LDT)
#define STAGE_E (2*TILE_E)        // A, B

template<bool HALF_OUT>
__global__ __launch_bounds__(256, 2)
void mma_gemm_fp16_kernel(const __half* __restrict__ A, const __half* __restrict__ B,
                          const float* __restrict__ bias, void* __restrict__ Cv,
                          int M, int N, int K)
{
    extern __shared__ __half sm[];
    int tid = threadIdx.x;
    int lane = tid & 31, wid = tid >> 5;
    int wm = wid & 1, wn = wid >> 1;
    int m0 = blockIdx.y * 128, n0 = blockIdx.x * 128;
    int NC = K / KC;
    uint32_t sb = smem_u32(sm);

    float acc[4][4][4];
#pragma unroll
    for (int mt = 0; mt < 4; mt++)
#pragma unroll
        for (int nt = 0; nt < 4; nt++)
#pragma unroll
            for (int r = 0; r < 4; r++) acc[mt][nt][r] = 0.0f;

    // load k-chunk kc into stage stg: 2048 16B chunks, 8/thread
    auto issue = [&](int kc, int stg) {
#pragma unroll
        for (int i = 0; i < 8; i++) {
            int c = tid + (i << 8);
            int tile = c >> 10;              // 0=A 1=B
            int r = (c >> 3) & 127;
            int q = c & 7;
            uint32_t sa = sb + (uint32_t)(stg * STAGE_E + tile * TILE_E + r * LDT + q * 8) * 2;
            const __half* g = (tile == 0) ? (A + (size_t)(m0 + r) * K)
                                          : (B + (size_t)(n0 + r) * K);
            g += kc * KC + q * 8;
            asm volatile("cp.async.cg.shared.global [%0], [%1], 16;" :: "r"(sa), "l"(g));
        }
        asm volatile("cp.async.commit_group;" ::: "memory");
    };

    issue(0, 0);

    for (int kc = 0; kc < NC; kc++) {
        int stg = kc & 1;
        if (kc + 1 < NC) issue(kc + 1, (kc + 1) & 1);
        if (kc + 1 < NC)
            asm volatile("cp.async.wait_group 1;" ::: "memory");
        else
            asm volatile("cp.async.wait_group 0;" ::: "memory");
        __syncthreads();

        uint32_t abase = sb + (uint32_t)(stg * STAGE_E) * 2
                       + (uint32_t)((wm * 64 + (lane & 15)) * LDT + (lane >> 4) * 8) * 2;
        uint32_t bbase = sb + (uint32_t)(stg * STAGE_E + TILE_E) * 2
                       + (uint32_t)((wn * 32 + (lane & 15)) * LDT + (lane >> 4) * 8) * 2;

#pragma unroll
        for (int kt = 0; kt < 4; kt++) {
            uint32_t kb = (uint32_t)(kt * 16) * 2;
            uint32_t ah[4][4], bh[2][4];
#pragma unroll
            for (int mt = 0; mt < 4; mt++)
                ldsm4(ah[mt], abase + (uint32_t)(mt * 16 * LDT) * 2 + kb);
#pragma unroll
            for (int nt2 = 0; nt2 < 2; nt2++)
                ldsm4(bh[nt2], bbase + (uint32_t)(nt2 * 16 * LDT) * 2 + kb);
#pragma unroll
            for (int mt = 0; mt < 4; mt++)
#pragma unroll
                for (int nt = 0; nt < 4; nt++) {
                    int n2 = nt >> 1, hf = nt & 1;
                    mma16816h(acc[mt][nt], ah[mt], bh[n2][hf], bh[n2][hf + 2]);
                }
        }
        __syncthreads();
    }

#pragma unroll
    for (int mt = 0; mt < 4; mt++) {
        int row = m0 + wm * 64 + mt * 16 + (lane >> 2);
#pragma unroll
        for (int nt = 0; nt < 4; nt++) {
            int col = n0 + wn * 32 + nt * 8 + (lane & 3) * 2;
            float b0 = bias[col], b1 = bias[col + 1];
            float v0 = acc[mt][nt][0] + b0, v1 = acc[mt][nt][1] + b1;
            float v2 = acc[mt][nt][2] + b0, v3 = acc[mt][nt][3] + b1;
            if (HALF_OUT) {
                __half* C = (__half*)Cv;
                *(uint32_t*)&C[(size_t)row * N + col]       = packhf(v0, v1);
                *(uint32_t*)&C[(size_t)(row + 8) * N + col] = packhf(v2, v3);
            } else {
                float* C = (float*)Cv;
                *(float2*)&C[(size_t)row * N + col]       = make_float2(v0, v1);
                *(float2*)&C[(size_t)(row + 8) * N + col] = make_float2(v2, v3);
            }
        }
    }
}

// ---------------- RoPE cos/sin table ----------------
__global__ void rope_table_kernel() {
    __shared__ double sinv[32];
    int t = threadIdx.x;
    if (t < 32)
        sinv[t] = exp2(-(double)(2 * t) / 64.0 * 13.287712379549449);  // log2(10000)
    __syncthreads();
    int idx = blockIdx.x * blockDim.x + t;
    if (idx >= Sm * DHm) return;
    int s = idx >> 6, d = idx & 63, i = d & 31;
    double ang = fmod((double)s * sinv[i], 6.283185307179586476925287);
    float sn, cs;
    sincosf((float)ang, &sn, &cs);
    g_cos[idx] = cs;
    g_sin[idx] = sn;
}

// ---------------- fused RoPE + scatter -> fp16 q/k/v in [B,H,S,Dh] ----------------
__global__ void rope_split_kernel() {
    int idx = blockIdx.x * blockDim.x + threadIdx.x;
    int d = idx & 63;
    int h = (idx >> 6) & 15;
    int s = (idx >> 10) & 2047;
    int b = idx >> 21;
    int base = (b * Sm + s) * QKVN + h * DHm;
    float c  = g_cos[(s << 6) + d];
    float sn = g_sin[(s << 6) + d];
    int dp = d ^ 32;
    float sgn = (d < 32) ? -1.0f : 1.0f;
    float q  = __half2float(g_qkvh[base + d]);
    float qp = __half2float(g_qkvh[base + dp]);
    float k  = __half2float(g_qkvh[base + Dm + d]);
    float kp = __half2float(g_qkvh[base + Dm + dp]);
    __half v = g_qkvh[base + 2 * Dm + d];
    float qr = fmaf(q, c, sgn * qp * sn);
    float kr = fmaf(k, c, sgn * kp * sn);
    int o = ((b * Hm + h) * Sm + s) * DHm + d;
    g_qf[o] = __float2half(qr);
    g_kf[o] = __float2half(kr);
    g_vf[o] = v;
}

// ---------------- flash attention on mma.sync fp16 (causal) ----------------
// 128 Q rows per CTA, 8 warps x 16 rows, 64-col K/V tiles, double-buffered cp.async.
#define LDK 72
#define QSZ (128*LDK)
#define KSZ (64*LDK)
#define STG (2*KSZ)              // kf, vf

__global__ __launch_bounds__(256, 2)
void attn_mma_kernel() {
    extern __shared__ __half asm_[];
    uint32_t sb = smem_u32(asm_);
    int tid = threadIdx.x;
    int lane = tid & 31, w = tid >> 5;
    int bh = blockIdx.y;
    int bidx = bh >> 4, hidx = bh & 15;
    int i0 = blockIdx.x * 128;
    int wr0 = w * 16;
    int ntiles = 2 * blockIdx.x + 2;
    const float SC = 0.125f;

    auto issue_kv = [&](int jt, int stg) {
        int j0 = jt * 64;
#pragma unroll
        for (int i = 0; i < 4; i++) {
            int c = tid + (i << 8);
            int tile = c >> 9;               // 0=kf 1=vf
            int r = (c >> 3) & 63;
            int q = c & 7;
            uint32_t sa = sb + (uint32_t)(QSZ + stg * STG + tile * KSZ + r * LDK + q * 8) * 2;
            const __half* g = (tile == 0) ? g_kf : g_vf;
            g += ((size_t)bh * Sm + j0 + r) * DHm + q * 8;
            asm volatile("cp.async.cg.shared.global [%0], [%1], 16;" :: "r"(sa), "l"(g));
        }
        asm volatile("cp.async.commit_group;" ::: "memory");
    };

#pragma unroll
    for (int i = 0; i < 4; i++) {
        int c = tid + (i << 8);
        int r = c >> 3, q = c & 7;
        uint32_t sa = sb + (uint32_t)(r * LDK + q * 8) * 2;
        const __half* g = g_qf + ((size_t)bh * Sm + i0 + r) * DHm + q * 8;
        asm volatile("cp.async.cg.shared.global [%0], [%1], 16;" :: "r"(sa), "l"(g));
    }
    issue_kv(0, 0);
    asm volatile("cp.async.commit_group;" ::: "memory");

    float O[8][4];
#pragma unroll
    for (int nt = 0; nt < 8; nt++)
#pragma unroll
        for (int r = 0; r < 4; r++) O[nt][r] = 0.0f;
    float m_lo = -1e30f, m_hi = -1e30f, l_lo = 0.0f, l_hi = 0.0f;

    int gi_lo = i0 + wr0 + (lane >> 2);
    int gi_hi = gi_lo + 8;
    int colb = (lane & 3) << 1;

    for (int jt = 0; jt < ntiles; jt++) {
        int stg = jt & 1;
        int j0 = jt * 64;
        if (jt + 1 < ntiles) issue_kv(jt + 1, (jt + 1) & 1);
        if (jt + 1 < ntiles)
            asm volatile("cp.async.wait_group 1;" ::: "memory");
        else
            asm volatile("cp.async.wait_group 0;" ::: "memory");
        __syncthreads();

        bool skip = (j0 > i0 + wr0 + 15);
        if (!skip) {
            uint32_t SB2 = QSZ + stg * STG;
            float c[8][4];
#pragma unroll
            for (int nt = 0; nt < 8; nt++)
#pragma unroll
                for (int r = 0; r < 4; r++) c[nt][r] = 0.0f;

            uint32_t qoffe = (uint32_t)((wr0 + (lane & 15)) * LDK + (lane >> 4) * 8);
            uint32_t koffe = (uint32_t)(((lane & 15)) * LDK + (lane >> 4) * 8);
#pragma unroll
            for (int kc = 0; kc < 4; kc++) {
                uint32_t qa = sb + (qoffe + kc * 16) * 2;
                uint32_t qah[4];
                ldsm4(qah, qa);
#pragma unroll
                for (int np = 0; np < 4; np++) {
                    uint32_t ka = sb + (SB2 + np * 16 * LDK + koffe + kc * 16) * 2;
                    uint32_t kbh[4];
                    ldsm4(kbh, ka);
                    mma16816h(c[2*np],   qah, kbh[0], kbh[2]);
                    mma16816h(c[2*np+1], qah, kbh[1], kbh[3]);
                }
            }

            bool needmask = (j0 + 63) > (i0 + wr0);
            float mxlo = -1e30f, mxhi = -1e30f;
#pragma unroll
            for (int nt = 0; nt < 8; nt++) {
                float s0 = c[nt][0] * SC, s1 = c[nt][1] * SC;
                float s2 = c[nt][2] * SC, s3 = c[nt][3] * SC;
                if (needmask) {
                    int j = j0 + nt * 8 + colb;
                    if (j     > gi_lo) s0 = -1e30f;
                    if (j + 1 > gi_lo) s1 = -1e30f;
                    if (j     > gi_hi) s2 = -1e30f;
                    if (j + 1 > gi_hi) s3 = -1e30f;
                }
                c[nt][0] = s0; c[nt][1] = s1; c[nt][2] = s2; c[nt][3] = s3;
                mxlo = fmaxf(mxlo, fmaxf(s0, s1));
                mxhi = fmaxf(mxhi, fmaxf(s2, s3));
            }
            mxlo = fmaxf(mxlo, __shfl_xor_sync(0xffffffffu, mxlo, 1));
            mxlo = fmaxf(mxlo, __shfl_xor_sync(0xffffffffu, mxlo, 2));
            mxhi = fmaxf(mxhi, __shfl_xor_sync(0xffffffffu, mxhi, 1));
            mxhi = fmaxf(mxhi, __shfl_xor_sync(0xffffffffu, mxhi, 2));
            float mnlo = fmaxf(m_lo, mxlo), mnhi = fmaxf(m_hi, mxhi);
            float alo = __expf(m_lo - mnlo), ahi = __expf(m_hi - mnhi);
            float slo = 0.0f, shi = 0.0f;
#pragma unroll
            for (int nt = 0; nt < 8; nt++) {
                float p0 = __expf(c[nt][0] - mnlo);
                float p1 = __expf(c[nt][1] - mnlo);
                float p2 = __expf(c[nt][2] - mnhi);
                float p3 = __expf(c[nt][3] - mnhi);
                c[nt][0] = p0; c[nt][1] = p1; c[nt][2] = p2; c[nt][3] = p3;
                slo += p0 + p1; shi += p2 + p3;
            }
            slo += __shfl_xor_sync(0xffffffffu, slo, 1);
            slo += __shfl_xor_sync(0xffffffffu, slo, 2);
            shi += __shfl_xor_sync(0xffffffffu, shi, 1);
            shi += __shfl_xor_sync(0xffffffffu, shi, 2);
            l_lo = l_lo * alo + slo; m_lo = mnlo;
            l_hi = l_hi * ahi + shi; m_hi = mnhi;
#pragma unroll
            for (int nt = 0; nt < 8; nt++) {
                O[nt][0] *= alo; O[nt][1] *= alo;
                O[nt][2] *= ahi; O[nt][3] *= ahi;
            }

            uint32_t pah[4][4];
#pragma unroll
            for (int kc = 0; kc < 4; kc++) {
#pragma unroll
                for (int half = 0; half < 2; half++) {
                    int nt = 2 * kc + half;
                    pah[kc][half * 2 + 0] = packhf(c[nt][0], c[nt][1]);
                    pah[kc][half * 2 + 1] = packhf(c[nt][2], c[nt][3]);
                }
            }

#pragma unroll
            for (int kc = 0; kc < 4; kc++) {
                uint32_t voffe = (uint32_t)(SB2 + KSZ + (kc * 16 + (lane & 15)) * LDK
                                            + (lane >> 4) * 8);
#pragma unroll
                for (int np = 0; np < 4; np++) {
                    uint32_t va = sb + (voffe + np * 16) * 2;
                    uint32_t vbh[4];
                    ldsm4t(vbh, va);
                    mma16816h(O[2*np],   pah[kc], vbh[0], vbh[1]);
                    mma16816h(O[2*np+1], pah[kc], vbh[2], vbh[3]);
                }
            }
        }
        __syncthreads();
    }

    float ivlo = 1.0f / l_lo, ivhi = 1.0f / l_hi;
    size_t rlo = (size_t)(bidx * Sm + gi_lo) * Dm;
    size_t rhi = (size_t)(bidx * Sm + gi_hi) * Dm;
#pragma unroll
    for (int nt = 0; nt < 8; nt++) {
        int col = hidx * DHm + nt * 8 + colb;
        *(uint32_t*)&g_cf[rlo + col] = packhf(O[nt][0] * ivlo, O[nt][1] * ivlo);
        *(uint32_t*)&g_cf[rhi + col] = packhf(O[nt][2] * ivhi, O[nt][3] * ivhi);
    }
}

// ---------------- launch ----------------
extern "C" void kernel_launch(void* const* d_in, const int* in_sizes, int n_in,
                              void* d_out, int out_size)
{
    const float* x      = (const float*)d_in[0];
    const float* qkv_w  = (const float*)d_in[1];
    const float* qkv_b  = (const float*)d_in[2];
    const float* proj_w = (const float*)d_in[3];
    const float* proj_b = (const float*)d_in[4];
    float* out = (float*)d_out;

    __half *p_xf, *p_wf, *p_pf, *p_qkvh, *p_cf;
    cudaGetSymbolAddress((void**)&p_xf, g_xf);
    cudaGetSymbolAddress((void**)&p_wf, g_wf);
    cudaGetSymbolAddress((void**)&p_pf, g_pf);
    cudaGetSymbolAddress((void**)&p_qkvh, g_qkvh);
    cudaGetSymbolAddress((void**)&p_cf, g_cf);

    int smem_gemm = 2 * STAGE_E * sizeof(__half);          // 73728
    cudaFuncSetAttribute(mma_gemm_fp16_kernel<true>,
                         cudaFuncAttributeMaxDynamicSharedMemorySize, smem_gemm);
    cudaFuncSetAttribute(mma_gemm_fp16_kernel<false>,
                         cudaFuncAttributeMaxDynamicSharedMemorySize, smem_gemm);
    int smem_attn = (QSZ + 2 * STG) * sizeof(__half);      // 55296
    cudaFuncSetAttribute(attn_mma_kernel, cudaFuncAttributeMaxDynamicSharedMemorySize, smem_attn);

    // 1) convert inputs to fp16 + rope table
    conv_all_kernel<<<(N1 + N2 + N3 + 255) / 256, 256>>>(x, qkv_w, proj_w);
    rope_table_kernel<<<(Sm * DHm + 255) / 256, 256>>>();

    // 2) QKV GEMM (fp16 single-pass, fp16 out)
    mma_gemm_fp16_kernel<true><<<dim3(QKVN / 128, MROWS / 128), 256, smem_gemm>>>(
        p_xf, p_wf, qkv_b, p_qkvh, MROWS, QKVN, Dm);

    // 3) fused rope/scatter
    rope_split_kernel<<<(Bm * Sm * Hm * DHm) / 256, 256>>>();

    // 4) flash attention (fp16 mma) -> g_cf
    attn_mma_kernel<<<dim3(Sm / 128, Bm * Hm), 256, smem_attn>>>();

    // 5) proj GEMM (fp16 single-pass, fp32 out)
    mma_gemm_fp16_kernel<false><<<dim3(Dm / 128, MROWS / 128), 256, smem_gemm>>>(
        p_cf, p_pf, proj_b, out, MROWS, Dm, Dm);
}